// round 4
// baseline (speedup 1.0000x reference)
#include <cuda_runtime.h>
#include <cuda_bf16.h>
#include <math.h>
#include <stdint.h>

#define B_    4
#define N_    2048
#define H_    16
#define DH    64
#define DM    1024
#define M_TOT (B_ * N_)        // 8192
#define QKV_N (3 * DM)         // 3072
#define NROWS (B_ * H_ * N_)   // 131072

typedef __nv_bfloat16 bf16;

// ---------------------------------------------------------------------------
// Scratch (static device globals — allocation-free per harness rules)
// ---------------------------------------------------------------------------
__device__ float g_q [(size_t)NROWS * DH];          // [B,H,N,Dh] raw q (pre-norm)
__device__ float g_k [(size_t)NROWS * DH];          // [B,H,N,Dh] raw k

__device__ bf16 g_qh[(size_t)NROWS * DH];           // normalized*scale q hi/lo
__device__ bf16 g_ql[(size_t)NROWS * DH];
__device__ bf16 g_kh[(size_t)NROWS * DH];           // normalized k hi/lo
__device__ bf16 g_kl[(size_t)NROWS * DH];
__device__ bf16 g_vth[(size_t)B_ * H_ * DH * N_];   // V^T hi/lo [B*H, Dh, N]
__device__ bf16 g_vtl[(size_t)B_ * H_ * DH * N_];

__device__ bf16 g_x_hi [(size_t)M_TOT * DM];
__device__ bf16 g_x_lo [(size_t)M_TOT * DM];
__device__ bf16 g_wq_hi[(size_t)QKV_N * DM];
__device__ bf16 g_wq_lo[(size_t)QKV_N * DM];
__device__ bf16 g_wo_hi[(size_t)DM * DM];
__device__ bf16 g_wo_lo[(size_t)DM * DM];
__device__ bf16 g_aoh[(size_t)M_TOT * DM];          // attention out hi/lo [B*N, DM]
__device__ bf16 g_aol[(size_t)M_TOT * DM];

// ---------------------------------------------------------------------------
// Helpers
// ---------------------------------------------------------------------------
__device__ __forceinline__ void mma_bf16(float* c, const uint32_t* a,
                                         uint32_t b0, uint32_t b1) {
    asm volatile(
        "mma.sync.aligned.m16n8k16.row.col.f32.bf16.bf16.f32 "
        "{%0,%1,%2,%3}, {%4,%5,%6,%7}, {%8,%9}, {%0,%1,%2,%3};\n"
        : "+f"(c[0]), "+f"(c[1]), "+f"(c[2]), "+f"(c[3])
        : "r"(a[0]), "r"(a[1]), "r"(a[2]), "r"(a[3]), "r"(b0), "r"(b1));
}
__device__ __forceinline__ uint32_t pack_bf16(float x, float y) {
    __nv_bfloat162 t = __floats2bfloat162_rn(x, y);
    return *(uint32_t*)&t;
}
__device__ __forceinline__ float bf16_round(float x) {
    return __bfloat162float(__float2bfloat16_rn(x));
}
__device__ __forceinline__ uint32_t smem_u32(const void* p) {
    uint32_t a;
    asm("{ .reg .u64 t; cvta.to.shared.u64 t, %1; cvt.u32.u64 %0, t; }" : "=r"(a) : "l"(p));
    return a;
}
__device__ __forceinline__ void cp16(uint32_t dst, const void* src) {
    asm volatile("cp.async.cg.shared.global [%0], [%1], 16;" :: "r"(dst), "l"(src));
}
#define CP_COMMIT() asm volatile("cp.async.commit_group;" ::: "memory")
#define CP_WAIT0()  asm volatile("cp.async.wait_group 0;" ::: "memory")

// padded row stride (halfwords) for conflict-free fragment loads
#define LDK 72

// ---------------------------------------------------------------------------
// f32 -> (bf16 hi, bf16 lo).  4 elems / thread.
// ---------------------------------------------------------------------------
__global__ __launch_bounds__(256) void decomp_kernel(
    const float* __restrict__ src, bf16* __restrict__ hi, bf16* __restrict__ lo)
{
    size_t i = ((size_t)blockIdx.x * 256 + threadIdx.x) * 4;
    float4 v = *(const float4*)(src + i);
    float h0 = bf16_round(v.x), h1 = bf16_round(v.y);
    float h2 = bf16_round(v.z), h3 = bf16_round(v.w);
    *(uint32_t*)(hi + i)     = pack_bf16(v.x, v.y);
    *(uint32_t*)(hi + i + 2) = pack_bf16(v.z, v.w);
    *(uint32_t*)(lo + i)     = pack_bf16(v.x - h0, v.y - h1);
    *(uint32_t*)(lo + i + 2) = pack_bf16(v.z - h2, v.w - h3);
}

// ---------------------------------------------------------------------------
// EC bf16 GEMM, cp.async double-buffered.  C[m,n] = sum_k A[m,k]*B[n,k]
// Block 128x128, 256 thr (8 warps 4x2), K-chunk 64, 2 stages.
// mode 0: QKV epilogue (bias; q,k -> float; v -> transposed bf16 hi/lo)
// mode 1: row-major float store to Cout
// ---------------------------------------------------------------------------
#define G_ARR   (128 * LDK * 2)            // 18432 B per array
#define G_STAGE (4 * G_ARR)                // 73728 B per stage
#define G_AH 0
#define G_AL (1 * G_ARR)
#define G_BH (2 * G_ARR)
#define G_BL (3 * G_ARR)
#define GS_TOTAL (2 * G_STAGE)             // 147456 B

__global__ __launch_bounds__(256) void gemm_mma_kernel(
    const bf16* __restrict__ Ahi, const bf16* __restrict__ Alo,
    const bf16* __restrict__ Bhi, const bf16* __restrict__ Blo,
    const float* __restrict__ bias, float* __restrict__ Cout, int mode)
{
    extern __shared__ char smem[];
    const uint32_t sbase = smem_u32(smem);
    const int tid  = threadIdx.x;
    const int wid  = tid >> 5;
    const int lane = tid & 31;
    const int wm   = wid & 3;
    const int wn   = wid >> 2;
    const int qd   = lane & 3;
    const int r4   = lane >> 2;
    const int m0 = blockIdx.y * 128;
    const int n0 = blockIdx.x * 128;

    const int row  = tid >> 1;
    const int half = tid & 1;
    const size_t gA0 = ((size_t)(m0 + row) * DM + half * 32) * 2;   // bytes
    const size_t gB0 = ((size_t)(n0 + row) * DM + half * 32) * 2;
    const uint32_t sRow = (uint32_t)(row * LDK + half * 32) * 2;

    float c[2][8][4];
#pragma unroll
    for (int mt = 0; mt < 2; mt++)
#pragma unroll
        for (int nt = 0; nt < 8; nt++)
#pragma unroll
            for (int j = 0; j < 4; j++) c[mt][nt][j] = 0.f;

    // issue stage for chunk ch into buffer buf
    auto issue = [&](int ch, int buf) {
        const size_t ko = (size_t)ch * 128;               // 64 bf16 = 128 bytes
        const uint32_t sb = sbase + buf * G_STAGE + sRow;
#pragma unroll
        for (int i = 0; i < 4; i++) {
            cp16(sb + G_AH + i * 16, (const char*)Ahi + gA0 + ko + i * 16);
            cp16(sb + G_AL + i * 16, (const char*)Alo + gA0 + ko + i * 16);
            cp16(sb + G_BH + i * 16, (const char*)Bhi + gB0 + ko + i * 16);
            cp16(sb + G_BL + i * 16, (const char*)Blo + gB0 + ko + i * 16);
        }
        CP_COMMIT();
    };

    issue(0, 0);

    for (int ch = 0; ch < 16; ch++) {
        const int buf = ch & 1;
        CP_WAIT0();
        __syncthreads();
        if (ch < 15) issue(ch + 1, buf ^ 1);

        const char* s = smem + buf * G_STAGE;
#pragma unroll
        for (int ks = 0; ks < 4; ks++) {
            uint32_t ah[2][4], al[2][4];
#pragma unroll
            for (int mt = 0; mt < 2; mt++) {
                int base = (wm * 32 + mt * 16 + r4) * LDK + ks * 16 + qd * 2;
                ah[mt][0] = *(uint32_t*)(s + G_AH + base * 2);
                ah[mt][1] = *(uint32_t*)(s + G_AH + (base + 8 * LDK) * 2);
                ah[mt][2] = *(uint32_t*)(s + G_AH + (base + 8) * 2);
                ah[mt][3] = *(uint32_t*)(s + G_AH + (base + 8 * LDK + 8) * 2);
                al[mt][0] = *(uint32_t*)(s + G_AL + base * 2);
                al[mt][1] = *(uint32_t*)(s + G_AL + (base + 8 * LDK) * 2);
                al[mt][2] = *(uint32_t*)(s + G_AL + (base + 8) * 2);
                al[mt][3] = *(uint32_t*)(s + G_AL + (base + 8 * LDK + 8) * 2);
            }
#pragma unroll
            for (int nt = 0; nt < 8; nt++) {
                int base = (wn * 64 + nt * 8 + r4) * LDK + ks * 16 + qd * 2;
                uint32_t bh0 = *(uint32_t*)(s + G_BH + base * 2);
                uint32_t bh1 = *(uint32_t*)(s + G_BH + (base + 8) * 2);
                uint32_t bl0 = *(uint32_t*)(s + G_BL + base * 2);
                uint32_t bl1 = *(uint32_t*)(s + G_BL + (base + 8) * 2);
#pragma unroll
                for (int mt = 0; mt < 2; mt++) {
                    mma_bf16(c[mt][nt], ah[mt], bh0, bh1);
                    mma_bf16(c[mt][nt], ah[mt], bl0, bl1);
                    mma_bf16(c[mt][nt], al[mt], bh0, bh1);
                }
            }
        }
        __syncthreads();
    }

    // ---- epilogue ----
#pragma unroll
    for (int nt = 0; nt < 8; nt++) {
        const int nb = n0 + wn * 64 + nt * 8 + qd * 2;
        if (mode == 0) {
            const int which = nb >> 10;
            const int rem   = nb & 1023;
            const int hh    = rem >> 6;
            const int d     = rem & 63;
            const float b0 = bias[nb], b1 = bias[nb + 1];
#pragma unroll
            for (int mt = 0; mt < 2; mt++) {
#pragma unroll
                for (int rr = 0; rr < 2; rr++) {
                    const int m = m0 + wm * 32 + mt * 16 + r4 + rr * 8;
                    const int bidx = m >> 11, ntok = m & 2047;
                    float f0 = c[mt][nt][rr * 2 + 0] + b0;
                    float f1 = c[mt][nt][rr * 2 + 1] + b1;
                    if (which < 2) {
                        const size_t sidx = ((size_t)(bidx * H_ + hh) * N_ + ntok) * DH + d;
                        float* dst = (which == 0) ? g_q : g_k;
                        *(float2*)(dst + sidx) = make_float2(f0, f1);
                    } else {
                        // transposed V store: [B*H, Dh, N]
                        const size_t vidx = ((size_t)(bidx * H_ + hh) * DH + d) * N_ + ntok;
                        g_vth[vidx]      = __float2bfloat16_rn(f0);
                        g_vtl[vidx]      = __float2bfloat16_rn(f0 - bf16_round(f0));
                        g_vth[vidx + N_] = __float2bfloat16_rn(f1);
                        g_vtl[vidx + N_] = __float2bfloat16_rn(f1 - bf16_round(f1));
                    }
                }
            }
        } else {
#pragma unroll
            for (int mt = 0; mt < 2; mt++) {
#pragma unroll
                for (int rr = 0; rr < 2; rr++) {
                    const int m = m0 + wm * 32 + mt * 16 + r4 + rr * 8;
                    *(float2*)(Cout + (size_t)m * DM + nb) =
                        make_float2(c[mt][nt][rr * 2 + 0], c[mt][nt][rr * 2 + 1]);
                }
            }
        }
    }
}

// ---------------------------------------------------------------------------
// L2 normalize rows of 64 + bf16 hi/lo emit. which 0: q (scale folded), 1: k.
// ---------------------------------------------------------------------------
__global__ __launch_bounds__(256) void l2norm_kernel(const float* __restrict__ lscale,
                                                     int which)
{
    const int warp = (blockIdx.x * blockDim.x + threadIdx.x) >> 5;
    const int lane = threadIdx.x & 31;
    if (warp >= NROWS) return;
    const float* row = (which ? g_k : g_q) + (size_t)warp * DH;
    float2 v = *(const float2*)(row + 2 * lane);
    float ss = v.x * v.x + v.y * v.y;
#pragma unroll
    for (int off = 16; off >= 1; off >>= 1)
        ss += __shfl_xor_sync(0xffffffffu, ss, off);
    float sc = 1.f;
    if (which == 0) {
        const int h = (warp >> 11) & (H_ - 1);
        sc = __expf(fminf(lscale[h], 4.6051702f));
    }
    const float inv = sc / fmaxf(sqrtf(ss), 1e-12f);
    const float f0 = v.x * inv, f1 = v.y * inv;
    bf16* hi = which ? g_kh : g_qh;
    bf16* lo = which ? g_kl : g_ql;
    const size_t idx = (size_t)warp * DH + 2 * lane;
    *(uint32_t*)(hi + idx) = pack_bf16(f0, f1);
    *(uint32_t*)(lo + idx) = pack_bf16(f0 - bf16_round(f0), f1 - bf16_round(f1));
}

// ---------------------------------------------------------------------------
// Flash attention, EC bf16 mma.sync. CTA = 256 thr (8 warps), Q block 128,
// K tile 64. V consumed pre-transposed ([B*H, Dh, N]).  2 CTAs/SM.
// smem: QH,QL 128*LDK*2 each; KH,KL,VTH,VTL 64*LDK*2 each = 73728 B.
// ---------------------------------------------------------------------------
#define A_QROWS 128
#define AS_QH 0
#define AS_QL (AS_QH + A_QROWS * LDK * 2)
#define AS_KH (AS_QL + A_QROWS * LDK * 2)      // 36864
#define AS_KL (AS_KH + 64 * LDK * 2)
#define AS_VH (AS_KL + 64 * LDK * 2)
#define AS_VL (AS_VH + 64 * LDK * 2)
#define AS_TOTAL (AS_VL + 64 * LDK * 2)        // 73728

__global__ __launch_bounds__(256, 2) void attn_mma_kernel()
{
    extern __shared__ char smem[];
    const uint32_t sbase = smem_u32(smem);
    const int tid  = threadIdx.x;
    const int wid  = tid >> 5;
    const int lane = tid & 31;
    const int qd   = lane & 3;
    const int r4   = lane >> 2;
    const int bh = blockIdx.y;
    const int b  = bh >> 4;
    const int h  = bh & 15;
    const int q0 = blockIdx.x * A_QROWS;

    const size_t rowbase = (size_t)bh * N_ * DH;    // elements
    const size_t vtbase  = (size_t)bh * DH * N_;

    // ---- Q tile load (cp.async, once) ----
    {
        const int r = tid >> 1, hf = tid & 1;
        const size_t off = (rowbase + (size_t)(q0 + r) * DH + hf * 32) * 2;
        const uint32_t sq = sbase + (uint32_t)(r * LDK + hf * 32) * 2;
#pragma unroll
        for (int i = 0; i < 4; i++) {
            cp16(sq + AS_QH + i * 16, (const char*)g_qh + off + i * 16);
            cp16(sq + AS_QL + i * 16, (const char*)g_ql + off + i * 16);
        }
        CP_COMMIT();
    }

    // K/V tile issue: 4 threads per row, 2 segs each
    const int kr = tid >> 2;               // 0..63
    const int ks0 = (tid & 3) * 2;         // seg pair
    auto issue_kv = [&](int j0) {
        const size_t koff = (rowbase + (size_t)(j0 + kr) * DH) * 2;       // K row kr
        const size_t voff = (vtbase + (size_t)kr * N_ + j0) * 2;          // Vt row d=kr
        const uint32_t skr = sbase + (uint32_t)(kr * LDK) * 2;
#pragma unroll
        for (int i = 0; i < 2; i++) {
            const int sgB = (ks0 + i) * 16;
            cp16(skr + AS_KH + sgB, (const char*)g_kh + koff + sgB);
            cp16(skr + AS_KL + sgB, (const char*)g_kl + koff + sgB);
            cp16(skr + AS_VH + sgB, (const char*)g_vth + voff + sgB);
            cp16(skr + AS_VL + sgB, (const char*)g_vtl + voff + sgB);
        }
        CP_COMMIT();
    };

    issue_kv(0);

    float o[8][4];
#pragma unroll
    for (int dn = 0; dn < 8; dn++)
#pragma unroll
        for (int j = 0; j < 4; j++) o[dn][j] = 0.f;
    float mrow0 = -INFINITY, mrow1 = -INFINITY, lrow0 = 0.f, lrow1 = 0.f;

    for (int j0 = 0; j0 < N_; j0 += 64) {
        CP_WAIT0();
        __syncthreads();

        // ---- S = Q K^T (EC) ----
        float s[8][4];
#pragma unroll
        for (int nt = 0; nt < 8; nt++)
#pragma unroll
            for (int j = 0; j < 4; j++) s[nt][j] = 0.f;

#pragma unroll
        for (int kk = 0; kk < 4; kk++) {
            uint32_t aqh[4], aql[4];
            {
                const int base = (wid * 16 + r4) * LDK + kk * 16 + qd * 2;
                aqh[0] = *(uint32_t*)(smem + AS_QH + base * 2);
                aqh[1] = *(uint32_t*)(smem + AS_QH + (base + 8 * LDK) * 2);
                aqh[2] = *(uint32_t*)(smem + AS_QH + (base + 8) * 2);
                aqh[3] = *(uint32_t*)(smem + AS_QH + (base + 8 * LDK + 8) * 2);
                aql[0] = *(uint32_t*)(smem + AS_QL + base * 2);
                aql[1] = *(uint32_t*)(smem + AS_QL + (base + 8 * LDK) * 2);
                aql[2] = *(uint32_t*)(smem + AS_QL + (base + 8) * 2);
                aql[3] = *(uint32_t*)(smem + AS_QL + (base + 8 * LDK + 8) * 2);
            }
#pragma unroll
            for (int nt = 0; nt < 8; nt++) {
                const int base = (nt * 8 + r4) * LDK + kk * 16 + qd * 2;
                uint32_t bh0 = *(uint32_t*)(smem + AS_KH + base * 2);
                uint32_t bh1 = *(uint32_t*)(smem + AS_KH + (base + 8) * 2);
                uint32_t bl0 = *(uint32_t*)(smem + AS_KL + base * 2);
                uint32_t bl1 = *(uint32_t*)(smem + AS_KL + (base + 8) * 2);
                mma_bf16(s[nt], aqh, bh0, bh1);
                mma_bf16(s[nt], aqh, bl0, bl1);
                mma_bf16(s[nt], aql, bh0, bh1);
            }
        }

        // ---- online softmax ----
        float mx0 = -INFINITY, mx1 = -INFINITY;
#pragma unroll
        for (int nt = 0; nt < 8; nt++) {
            mx0 = fmaxf(mx0, fmaxf(s[nt][0], s[nt][1]));
            mx1 = fmaxf(mx1, fmaxf(s[nt][2], s[nt][3]));
        }
        mx0 = fmaxf(mx0, __shfl_xor_sync(0xffffffffu, mx0, 1));
        mx0 = fmaxf(mx0, __shfl_xor_sync(0xffffffffu, mx0, 2));
        mx1 = fmaxf(mx1, __shfl_xor_sync(0xffffffffu, mx1, 1));
        mx1 = fmaxf(mx1, __shfl_xor_sync(0xffffffffu, mx1, 2));
        const float mnew0 = fmaxf(mrow0, mx0);
        const float mnew1 = fmaxf(mrow1, mx1);
        const float corr0 = __expf(mrow0 - mnew0);
        const float corr1 = __expf(mrow1 - mnew1);
        float rs0 = 0.f, rs1 = 0.f;
#pragma unroll
        for (int nt = 0; nt < 8; nt++) {
            s[nt][0] = __expf(s[nt][0] - mnew0);
            s[nt][1] = __expf(s[nt][1] - mnew0);
            s[nt][2] = __expf(s[nt][2] - mnew1);
            s[nt][3] = __expf(s[nt][3] - mnew1);
            rs0 += s[nt][0] + s[nt][1];
            rs1 += s[nt][2] + s[nt][3];
        }
        rs0 += __shfl_xor_sync(0xffffffffu, rs0, 1);
        rs0 += __shfl_xor_sync(0xffffffffu, rs0, 2);
        rs1 += __shfl_xor_sync(0xffffffffu, rs1, 1);
        rs1 += __shfl_xor_sync(0xffffffffu, rs1, 2);
        lrow0 = lrow0 * corr0 + rs0;
        lrow1 = lrow1 * corr1 + rs1;
        mrow0 = mnew0; mrow1 = mnew1;
#pragma unroll
        for (int dn = 0; dn < 8; dn++) {
            o[dn][0] *= corr0; o[dn][1] *= corr0;
            o[dn][2] *= corr1; o[dn][3] *= corr1;
        }

        // ---- O += P V (EC, P frags repacked from S frags) ----
#pragma unroll
        for (int kt = 0; kt < 4; kt++) {
            const int u = 2 * kt, v2 = 2 * kt + 1;
            uint32_t pah[4], pal[4];
            pah[0] = pack_bf16(s[u][0],  s[u][1]);
            pah[1] = pack_bf16(s[u][2],  s[u][3]);
            pah[2] = pack_bf16(s[v2][0], s[v2][1]);
            pah[3] = pack_bf16(s[v2][2], s[v2][3]);
            pal[0] = pack_bf16(s[u][0]  - bf16_round(s[u][0]),  s[u][1]  - bf16_round(s[u][1]));
            pal[1] = pack_bf16(s[u][2]  - bf16_round(s[u][2]),  s[u][3]  - bf16_round(s[u][3]));
            pal[2] = pack_bf16(s[v2][0] - bf16_round(s[v2][0]), s[v2][1] - bf16_round(s[v2][1]));
            pal[3] = pack_bf16(s[v2][2] - bf16_round(s[v2][2]), s[v2][3] - bf16_round(s[v2][3]));
#pragma unroll
            for (int dn = 0; dn < 8; dn++) {
                const int base = (dn * 8 + r4) * LDK + kt * 16 + qd * 2;
                uint32_t vh0 = *(uint32_t*)(smem + AS_VH + base * 2);
                uint32_t vh1 = *(uint32_t*)(smem + AS_VH + (base + 8) * 2);
                uint32_t vl0 = *(uint32_t*)(smem + AS_VL + base * 2);
                uint32_t vl1 = *(uint32_t*)(smem + AS_VL + (base + 8) * 2);
                mma_bf16(o[dn], pah, vh0, vh1);
                mma_bf16(o[dn], pah, vl0, vl1);
                mma_bf16(o[dn], pal, vh0, vh1);
            }
        }
        __syncthreads();
        if (j0 + 64 < N_) issue_kv(j0 + 64);
    }

    // ---- finalize: write ao hi/lo at [b*N+n][h*64+d] ----
    const float inv0 = 1.f / lrow0;
    const float inv1 = 1.f / lrow1;
#pragma unroll
    for (int dn = 0; dn < 8; dn++) {
        const int d = dn * 8 + qd * 2;
#pragma unroll
        for (int rr = 0; rr < 2; rr++) {
            const int n = q0 + wid * 16 + r4 + rr * 8;
            const float inv = rr ? inv1 : inv0;
            const float f0 = o[dn][rr * 2 + 0] * inv;
            const float f1 = o[dn][rr * 2 + 1] * inv;
            const size_t idx = (size_t)(b * N_ + n) * DM + h * 64 + d;
            *(uint32_t*)(g_aoh + idx) = pack_bf16(f0, f1);
            *(uint32_t*)(g_aol + idx) = pack_bf16(f0 - bf16_round(f0), f1 - bf16_round(f1));
        }
    }
}

// ---------------------------------------------------------------------------
extern "C" void kernel_launch(void* const* d_in, const int* in_sizes, int n_in,
                              void* d_out, int out_size)
{
    const float* x      = (const float*)d_in[0];
    const float* w_qkv  = (const float*)d_in[1];
    const float* b_qkv  = (const float*)d_in[2];
    const float* w_out  = (const float*)d_in[3];
    const float* lscale = (const float*)d_in[4];
    float* out = (float*)d_out;

    bf16 *xh, *xl, *wqh, *wql, *woh, *wol, *aoh, *aol;
    cudaGetSymbolAddress((void**)&xh,  g_x_hi);
    cudaGetSymbolAddress((void**)&xl,  g_x_lo);
    cudaGetSymbolAddress((void**)&wqh, g_wq_hi);
    cudaGetSymbolAddress((void**)&wql, g_wq_lo);
    cudaGetSymbolAddress((void**)&woh, g_wo_hi);
    cudaGetSymbolAddress((void**)&wol, g_wo_lo);
    cudaGetSymbolAddress((void**)&aoh, g_aoh);
    cudaGetSymbolAddress((void**)&aol, g_aol);

    cudaFuncSetAttribute(gemm_mma_kernel, cudaFuncAttributeMaxDynamicSharedMemorySize, GS_TOTAL);
    cudaFuncSetAttribute(attn_mma_kernel, cudaFuncAttributeMaxDynamicSharedMemorySize, AS_TOTAL);

    // 0. decompose inputs
    decomp_kernel<<<(M_TOT * DM) / 1024, 256>>>(x,     xh,  xl);
    decomp_kernel<<<(QKV_N * DM) / 1024, 256>>>(w_qkv, wqh, wql);
    decomp_kernel<<<(DM * DM)    / 1024, 256>>>(w_out, woh, wol);

    // 1. QKV projection: q,k -> float; v -> transposed bf16 hi/lo
    dim3 g1(QKV_N / 128, M_TOT / 128);     // (24, 64)
    gemm_mma_kernel<<<g1, 256, GS_TOTAL>>>(xh, xl, wqh, wql, b_qkv, nullptr, 0);

    // 2. normalize q (scale folded) and k, emit hi/lo
    l2norm_kernel<<<NROWS / 8, 256>>>(lscale, 0);
    l2norm_kernel<<<NROWS / 8, 256>>>(lscale, 1);

    // 3. flash attention -> ao hi/lo
    dim3 g3(N_ / A_QROWS, B_ * H_);        // (16, 64)
    attn_mma_kernel<<<g3, 256, AS_TOTAL>>>();

    // 4. output projection -> d_out
    dim3 g4(DM / 128, M_TOT / 128);        // (8, 64)
    gemm_mma_kernel<<<g4, 256, GS_TOTAL>>>(aoh, aol, woh, wol, nullptr, out, 1);
}

// round 5
// speedup vs baseline: 1.2668x; 1.2668x over previous
#include <cuda_runtime.h>
#include <cuda_bf16.h>
#include <math.h>
#include <stdint.h>

#define B_    4
#define N_    2048
#define H_    16
#define DH    64
#define DM    1024
#define M_TOT (B_ * N_)        // 8192
#define QKV_N (3 * DM)         // 3072
#define NROWS (B_ * H_ * N_)   // 131072

typedef __nv_bfloat16 bf16;

// ---------------------------------------------------------------------------
// Scratch (static device globals — allocation-free per harness rules)
// ---------------------------------------------------------------------------
__device__ float g_q [(size_t)NROWS * DH];          // [B,H,N,Dh] raw q (pre-norm)
__device__ float g_k [(size_t)NROWS * DH];          // [B,H,N,Dh] raw k

__device__ bf16 g_qh[(size_t)NROWS * DH];           // normalized*scale q hi/lo
__device__ bf16 g_ql[(size_t)NROWS * DH];
__device__ bf16 g_kh[(size_t)NROWS * DH];           // normalized k hi/lo
__device__ bf16 g_kl[(size_t)NROWS * DH];
__device__ bf16 g_vh[(size_t)NROWS * DH];           // v hi/lo ([B,H,N,Dh])
__device__ bf16 g_vl[(size_t)NROWS * DH];

__device__ bf16 g_x_hi [(size_t)M_TOT * DM];
__device__ bf16 g_x_lo [(size_t)M_TOT * DM];
__device__ bf16 g_wq_hi[(size_t)QKV_N * DM];
__device__ bf16 g_wq_lo[(size_t)QKV_N * DM];
__device__ bf16 g_wo_hi[(size_t)DM * DM];
__device__ bf16 g_wo_lo[(size_t)DM * DM];
__device__ bf16 g_aoh[(size_t)M_TOT * DM];          // attention out hi/lo [B*N, DM]
__device__ bf16 g_aol[(size_t)M_TOT * DM];

// ---------------------------------------------------------------------------
// mma.sync helpers (sm_80-era PTX — compiles for compute_103)
// ---------------------------------------------------------------------------
__device__ __forceinline__ void mma_bf16(float* c, const uint32_t* a,
                                         uint32_t b0, uint32_t b1) {
    asm volatile(
        "mma.sync.aligned.m16n8k16.row.col.f32.bf16.bf16.f32 "
        "{%0,%1,%2,%3}, {%4,%5,%6,%7}, {%8,%9}, {%0,%1,%2,%3};\n"
        : "+f"(c[0]), "+f"(c[1]), "+f"(c[2]), "+f"(c[3])
        : "r"(a[0]), "r"(a[1]), "r"(a[2]), "r"(a[3]), "r"(b0), "r"(b1));
}
__device__ __forceinline__ uint32_t pack_bf16(float x, float y) {
    __nv_bfloat162 t = __floats2bfloat162_rn(x, y);   // low = x, high = y
    return *(uint32_t*)&t;
}
__device__ __forceinline__ float bf16_round(float x) {
    return __bfloat162float(__float2bfloat16_rn(x));
}

// padded row stride (halfwords) for conflict-free fragment loads
#define LDK 72

// ---------------------------------------------------------------------------
// f32 -> (bf16 hi, bf16 lo).  4 elems / thread.
// ---------------------------------------------------------------------------
__global__ __launch_bounds__(256) void decomp_kernel(
    const float* __restrict__ src, bf16* __restrict__ hi, bf16* __restrict__ lo)
{
    size_t i = ((size_t)blockIdx.x * 256 + threadIdx.x) * 4;
    float4 v = *(const float4*)(src + i);
    float h0 = bf16_round(v.x), h1 = bf16_round(v.y);
    float h2 = bf16_round(v.z), h3 = bf16_round(v.w);
    *(uint32_t*)(hi + i)     = pack_bf16(v.x, v.y);
    *(uint32_t*)(hi + i + 2) = pack_bf16(v.z, v.w);
    *(uint32_t*)(lo + i)     = pack_bf16(v.x - h0, v.y - h1);
    *(uint32_t*)(lo + i + 2) = pack_bf16(v.z - h2, v.w - h3);
}

// ---------------------------------------------------------------------------
// EC bf16 GEMM via mma.sync:  C[m,n] = sum_k A[m,k]*B[n,k]  (+bias, scatter)
// Block 128x128, 256 thr (8 warps as 4x2), warp tile 32x64, K-chunk 64.
// __launch_bounds__(256,2): cap 128 regs so 2 CTAs/SM (cross-CTA overlap).
// mode 0: QKV epilogue (bias; q,k -> float g_q/g_k; v -> bf16 hi/lo g_vh/g_vl)
// mode 1: row-major float store to Cout [M,1024]
// ---------------------------------------------------------------------------
#define GS_AH 0
#define GS_AL (GS_AH + 128 * LDK * 2)
#define GS_BH (GS_AL + 128 * LDK * 2)
#define GS_BL (GS_BH + 128 * LDK * 2)
#define GS_TOTAL (GS_BL + 128 * LDK * 2)   // 73728 B

__global__ __launch_bounds__(256, 2) void gemm_mma_kernel(
    const bf16* __restrict__ Ahi, const bf16* __restrict__ Alo,
    const bf16* __restrict__ Bhi, const bf16* __restrict__ Blo,
    const float* __restrict__ bias, float* __restrict__ Cout, int mode)
{
    extern __shared__ char smem[];
    const int tid  = threadIdx.x;
    const int wid  = tid >> 5;
    const int lane = tid & 31;
    const int wm   = wid & 3;          // m quadrant (32 rows)
    const int wn   = wid >> 2;         // n half (64 cols)
    const int qd   = lane & 3;
    const int r4   = lane >> 2;
    const int m0 = blockIdx.y * 128;
    const int n0 = blockIdx.x * 128;

    float c[2][8][4];
#pragma unroll
    for (int mt = 0; mt < 2; mt++)
#pragma unroll
        for (int nt = 0; nt < 8; nt++)
#pragma unroll
            for (int j = 0; j < 4; j++) c[mt][nt][j] = 0.f;

    const int row  = tid >> 1;         // 0..127
    const int half = tid & 1;          // 32-elem half of the 64-col chunk

    for (int ch = 0; ch < 16; ch++) {
        // ---- load chunk (A rows m0+row, B rows n0+row; cols [64ch,64ch+64)) ----
        {
            const size_t aoff = ((size_t)(m0 + row) * DM + ch * 64 + half * 32) * 2;
            const size_t boff = ((size_t)(n0 + row) * DM + ch * 64 + half * 32) * 2;
            char* sA = smem + (row * LDK + half * 32) * 2;
#pragma unroll
            for (int i = 0; i < 4; i++) {
                *(uint4*)(sA + GS_AH + i * 16) = *(const uint4*)((const char*)Ahi + aoff + i * 16);
                *(uint4*)(sA + GS_AL + i * 16) = *(const uint4*)((const char*)Alo + aoff + i * 16);
                *(uint4*)(sA + GS_BH + i * 16) = *(const uint4*)((const char*)Bhi + boff + i * 16);
                *(uint4*)(sA + GS_BL + i * 16) = *(const uint4*)((const char*)Blo + boff + i * 16);
            }
        }
        __syncthreads();

#pragma unroll
        for (int ks = 0; ks < 4; ks++) {
            uint32_t ah[2][4], al[2][4];
#pragma unroll
            for (int mt = 0; mt < 2; mt++) {
                int base = (wm * 32 + mt * 16 + r4) * LDK + ks * 16 + qd * 2;
                ah[mt][0] = *(uint32_t*)(smem + GS_AH + base * 2);
                ah[mt][1] = *(uint32_t*)(smem + GS_AH + (base + 8 * LDK) * 2);
                ah[mt][2] = *(uint32_t*)(smem + GS_AH + (base + 8) * 2);
                ah[mt][3] = *(uint32_t*)(smem + GS_AH + (base + 8 * LDK + 8) * 2);
                al[mt][0] = *(uint32_t*)(smem + GS_AL + base * 2);
                al[mt][1] = *(uint32_t*)(smem + GS_AL + (base + 8 * LDK) * 2);
                al[mt][2] = *(uint32_t*)(smem + GS_AL + (base + 8) * 2);
                al[mt][3] = *(uint32_t*)(smem + GS_AL + (base + 8 * LDK + 8) * 2);
            }
#pragma unroll
            for (int nt = 0; nt < 8; nt++) {
                int base = (wn * 64 + nt * 8 + r4) * LDK + ks * 16 + qd * 2;
                uint32_t bh0 = *(uint32_t*)(smem + GS_BH + base * 2);
                uint32_t bh1 = *(uint32_t*)(smem + GS_BH + (base + 8) * 2);
                uint32_t bl0 = *(uint32_t*)(smem + GS_BL + base * 2);
                uint32_t bl1 = *(uint32_t*)(smem + GS_BL + (base + 8) * 2);
#pragma unroll
                for (int mt = 0; mt < 2; mt++) {
                    mma_bf16(c[mt][nt], ah[mt], bh0, bh1);
                    mma_bf16(c[mt][nt], ah[mt], bl0, bl1);
                    mma_bf16(c[mt][nt], al[mt], bh0, bh1);
                }
            }
        }
        __syncthreads();
    }

    // ---- epilogue ----
#pragma unroll
    for (int nt = 0; nt < 8; nt++) {
        const int nb = n0 + wn * 64 + nt * 8 + qd * 2;
        if (mode == 0) {
            const int which = nb >> 10;
            const int rem   = nb & 1023;
            const int hh    = rem >> 6;
            const int d     = rem & 63;
            const float b0 = bias[nb], b1 = bias[nb + 1];
#pragma unroll
            for (int mt = 0; mt < 2; mt++) {
#pragma unroll
                for (int rr = 0; rr < 2; rr++) {
                    const int m = m0 + wm * 32 + mt * 16 + r4 + rr * 8;
                    const int bidx = m >> 11, ntok = m & 2047;
                    const size_t sidx = ((size_t)(bidx * H_ + hh) * N_ + ntok) * DH + d;
                    float f0 = c[mt][nt][rr * 2 + 0] + b0;
                    float f1 = c[mt][nt][rr * 2 + 1] + b1;
                    if (which == 0)      *(float2*)(g_q + sidx) = make_float2(f0, f1);
                    else if (which == 1) *(float2*)(g_k + sidx) = make_float2(f0, f1);
                    else {
                        *(uint32_t*)(g_vh + sidx) = pack_bf16(f0, f1);
                        *(uint32_t*)(g_vl + sidx) = pack_bf16(f0 - bf16_round(f0),
                                                              f1 - bf16_round(f1));
                    }
                }
            }
        } else {
#pragma unroll
            for (int mt = 0; mt < 2; mt++) {
#pragma unroll
                for (int rr = 0; rr < 2; rr++) {
                    const int m = m0 + wm * 32 + mt * 16 + r4 + rr * 8;
                    *(float2*)(Cout + (size_t)m * DM + nb) =
                        make_float2(c[mt][nt][rr * 2 + 0], c[mt][nt][rr * 2 + 1]);
                }
            }
        }
    }
}

// ---------------------------------------------------------------------------
// L2 normalize rows of 64 + bf16 hi/lo emit. which 0: q (scale folded), 1: k.
// ---------------------------------------------------------------------------
__global__ __launch_bounds__(256) void l2norm_kernel(const float* __restrict__ lscale,
                                                     int which)
{
    const int warp = (blockIdx.x * blockDim.x + threadIdx.x) >> 5;
    const int lane = threadIdx.x & 31;
    if (warp >= NROWS) return;
    const float* row = (which ? g_k : g_q) + (size_t)warp * DH;
    float2 v = *(const float2*)(row + 2 * lane);
    float ss = v.x * v.x + v.y * v.y;
#pragma unroll
    for (int off = 16; off >= 1; off >>= 1)
        ss += __shfl_xor_sync(0xffffffffu, ss, off);
    float sc = 1.f;
    if (which == 0) {
        const int h = (warp >> 11) & (H_ - 1);
        sc = __expf(fminf(lscale[h], 4.6051702f));
    }
    const float inv = sc / fmaxf(sqrtf(ss), 1e-12f);
    const float f0 = v.x * inv, f1 = v.y * inv;
    bf16* hi = which ? g_kh : g_qh;
    bf16* lo = which ? g_kl : g_ql;
    const size_t idx = (size_t)warp * DH + 2 * lane;
    *(uint32_t*)(hi + idx) = pack_bf16(f0, f1);
    *(uint32_t*)(lo + idx) = pack_bf16(f0 - bf16_round(f0), f1 - bf16_round(f1));
}

// ---------------------------------------------------------------------------
// Flash attention, EC bf16 mma.sync. CTA = 128 thr (4 warps), Q block 64
// (16 rows/warp), K tile 64. Scale pre-folded into q. Emits ao hi/lo.
// __launch_bounds__(128,4): 4 CTAs/SM (221KB smem, 64K regs).
// smem (bytes): Qh,Ql,Kh,Kl,Vth,Vtl each 64*LDK*2 = 9216 -> 55296 total.
// ---------------------------------------------------------------------------
#define AS_QH 0
#define AS_QL (AS_QH + 64 * LDK * 2)
#define AS_KH (AS_QL + 64 * LDK * 2)
#define AS_KL (AS_KH + 64 * LDK * 2)
#define AS_VH (AS_KL + 64 * LDK * 2)
#define AS_VL (AS_VH + 64 * LDK * 2)
#define AS_TOTAL (AS_VL + 64 * LDK * 2)  // 55296

__global__ __launch_bounds__(128, 4) void attn_mma_kernel()
{
    extern __shared__ char smem[];
    const int tid  = threadIdx.x;
    const int wid  = tid >> 5;
    const int lane = tid & 31;
    const int qd   = lane & 3;
    const int r4   = lane >> 2;
    const int bh = blockIdx.y;
    const int b  = bh >> 4;
    const int h  = bh & 15;
    const int q0 = blockIdx.x * 64;

    const size_t rowbase = (size_t)bh * N_ * DH;

    // ---- load Q tile (scaled, normalized, hi/lo) ----
    {
        const int row = tid >> 1, half = tid & 1;
        const size_t off = (rowbase + (size_t)(q0 + row) * DH + half * 32) * 2;
        char* s = smem + (row * LDK + half * 32) * 2;
#pragma unroll
        for (int i = 0; i < 4; i++) {
            *(uint4*)(s + AS_QH + i * 16) = *(const uint4*)((const char*)g_qh + off + i * 16);
            *(uint4*)(s + AS_QL + i * 16) = *(const uint4*)((const char*)g_ql + off + i * 16);
        }
    }

    float o[8][4];
#pragma unroll
    for (int dn = 0; dn < 8; dn++)
#pragma unroll
        for (int j = 0; j < 4; j++) o[dn][j] = 0.f;
    float mrow0 = -INFINITY, mrow1 = -INFINITY, lrow0 = 0.f, lrow1 = 0.f;

    for (int j0 = 0; j0 < N_; j0 += 64) {
        // ---- load K tile (rows) ----
        {
            const int row = tid >> 1, half = tid & 1;
            const size_t off = (rowbase + (size_t)(j0 + row) * DH + half * 32) * 2;
            char* s = smem + (row * LDK + half * 32) * 2;
#pragma unroll
            for (int i = 0; i < 4; i++) {
                *(uint4*)(s + AS_KH + i * 16) = *(const uint4*)((const char*)g_kh + off + i * 16);
                *(uint4*)(s + AS_KL + i * 16) = *(const uint4*)((const char*)g_kl + off + i * 16);
            }
        }
        // ---- load V tile transposed: Vt[d][j], j pairs packed in u32 ----
        {
            const int jp = tid & 31, dq = tid >> 5;        // dq in 0..3 -> 16 d vals
            const size_t o0 = rowbase + (size_t)(j0 + 2 * jp) * DH + dq * 16;
            uint32_t uah[8], ubh[8], ual[8], ubl[8];
            *(uint4*)(uah)     = *(const uint4*)(g_vh + o0);
            *(uint4*)(uah + 4) = *(const uint4*)(g_vh + o0 + 8);
            *(uint4*)(ubh)     = *(const uint4*)(g_vh + o0 + DH);
            *(uint4*)(ubh + 4) = *(const uint4*)(g_vh + o0 + DH + 8);
            *(uint4*)(ual)     = *(const uint4*)(g_vl + o0);
            *(uint4*)(ual + 4) = *(const uint4*)(g_vl + o0 + 8);
            *(uint4*)(ubl)     = *(const uint4*)(g_vl + o0 + DH);
            *(uint4*)(ubl + 4) = *(const uint4*)(g_vl + o0 + DH + 8);
#pragma unroll
            for (int t = 0; t < 8; t++) {
                const int d0 = dq * 16 + 2 * t;
                uint32_t w0h = (uah[t] & 0xffffu) | (ubh[t] << 16);
                uint32_t w1h = (uah[t] >> 16)     | (ubh[t] & 0xffff0000u);
                uint32_t w0l = (ual[t] & 0xffffu) | (ubl[t] << 16);
                uint32_t w1l = (ual[t] >> 16)     | (ubl[t] & 0xffff0000u);
                *(uint32_t*)(smem + AS_VH + (d0 * LDK + 2 * jp) * 2)       = w0h;
                *(uint32_t*)(smem + AS_VH + ((d0 + 1) * LDK + 2 * jp) * 2) = w1h;
                *(uint32_t*)(smem + AS_VL + (d0 * LDK + 2 * jp) * 2)       = w0l;
                *(uint32_t*)(smem + AS_VL + ((d0 + 1) * LDK + 2 * jp) * 2) = w1l;
            }
        }
        __syncthreads();

        // ---- S = Q K^T (EC, 3 passes) ----
        float s[8][4];
#pragma unroll
        for (int nt = 0; nt < 8; nt++)
#pragma unroll
            for (int j = 0; j < 4; j++) s[nt][j] = 0.f;

#pragma unroll
        for (int ks = 0; ks < 4; ks++) {
            uint32_t aqh[4], aql[4];
            {
                const int base = (wid * 16 + r4) * LDK + ks * 16 + qd * 2;
                aqh[0] = *(uint32_t*)(smem + AS_QH + base * 2);
                aqh[1] = *(uint32_t*)(smem + AS_QH + (base + 8 * LDK) * 2);
                aqh[2] = *(uint32_t*)(smem + AS_QH + (base + 8) * 2);
                aqh[3] = *(uint32_t*)(smem + AS_QH + (base + 8 * LDK + 8) * 2);
                aql[0] = *(uint32_t*)(smem + AS_QL + base * 2);
                aql[1] = *(uint32_t*)(smem + AS_QL + (base + 8 * LDK) * 2);
                aql[2] = *(uint32_t*)(smem + AS_QL + (base + 8) * 2);
                aql[3] = *(uint32_t*)(smem + AS_QL + (base + 8 * LDK + 8) * 2);
            }
#pragma unroll
            for (int nt = 0; nt < 8; nt++) {
                const int base = (nt * 8 + r4) * LDK + ks * 16 + qd * 2;
                uint32_t bh0 = *(uint32_t*)(smem + AS_KH + base * 2);
                uint32_t bh1 = *(uint32_t*)(smem + AS_KH + (base + 8) * 2);
                uint32_t bl0 = *(uint32_t*)(smem + AS_KL + base * 2);
                uint32_t bl1 = *(uint32_t*)(smem + AS_KL + (base + 8) * 2);
                mma_bf16(s[nt], aqh, bh0, bh1);
                mma_bf16(s[nt], aqh, bl0, bl1);
                mma_bf16(s[nt], aql, bh0, bh1);
            }
        }

        // ---- online softmax (rows r4 / r4+8, replicated across quad) ----
        float mx0 = -INFINITY, mx1 = -INFINITY;
#pragma unroll
        for (int nt = 0; nt < 8; nt++) {
            mx0 = fmaxf(mx0, fmaxf(s[nt][0], s[nt][1]));
            mx1 = fmaxf(mx1, fmaxf(s[nt][2], s[nt][3]));
        }
        mx0 = fmaxf(mx0, __shfl_xor_sync(0xffffffffu, mx0, 1));
        mx0 = fmaxf(mx0, __shfl_xor_sync(0xffffffffu, mx0, 2));
        mx1 = fmaxf(mx1, __shfl_xor_sync(0xffffffffu, mx1, 1));
        mx1 = fmaxf(mx1, __shfl_xor_sync(0xffffffffu, mx1, 2));
        const float mnew0 = fmaxf(mrow0, mx0);
        const float mnew1 = fmaxf(mrow1, mx1);
        const float corr0 = __expf(mrow0 - mnew0);
        const float corr1 = __expf(mrow1 - mnew1);
        float rs0 = 0.f, rs1 = 0.f;
#pragma unroll
        for (int nt = 0; nt < 8; nt++) {
            s[nt][0] = __expf(s[nt][0] - mnew0);
            s[nt][1] = __expf(s[nt][1] - mnew0);
            s[nt][2] = __expf(s[nt][2] - mnew1);
            s[nt][3] = __expf(s[nt][3] - mnew1);
            rs0 += s[nt][0] + s[nt][1];
            rs1 += s[nt][2] + s[nt][3];
        }
        rs0 += __shfl_xor_sync(0xffffffffu, rs0, 1);
        rs0 += __shfl_xor_sync(0xffffffffu, rs0, 2);
        rs1 += __shfl_xor_sync(0xffffffffu, rs1, 1);
        rs1 += __shfl_xor_sync(0xffffffffu, rs1, 2);
        lrow0 = lrow0 * corr0 + rs0;
        lrow1 = lrow1 * corr1 + rs1;
        mrow0 = mnew0; mrow1 = mnew1;
#pragma unroll
        for (int dn = 0; dn < 8; dn++) {
            o[dn][0] *= corr0; o[dn][1] *= corr0;
            o[dn][2] *= corr1; o[dn][3] *= corr1;
        }

        // ---- O += P V (EC, P frags repacked from S frags) ----
#pragma unroll
        for (int kt = 0; kt < 4; kt++) {
            const int u = 2 * kt, v2 = 2 * kt + 1;
            uint32_t pah[4], pal[4];
            pah[0] = pack_bf16(s[u][0],  s[u][1]);
            pah[1] = pack_bf16(s[u][2],  s[u][3]);
            pah[2] = pack_bf16(s[v2][0], s[v2][1]);
            pah[3] = pack_bf16(s[v2][2], s[v2][3]);
            pal[0] = pack_bf16(s[u][0]  - bf16_round(s[u][0]),  s[u][1]  - bf16_round(s[u][1]));
            pal[1] = pack_bf16(s[u][2]  - bf16_round(s[u][2]),  s[u][3]  - bf16_round(s[u][3]));
            pal[2] = pack_bf16(s[v2][0] - bf16_round(s[v2][0]), s[v2][1] - bf16_round(s[v2][1]));
            pal[3] = pack_bf16(s[v2][2] - bf16_round(s[v2][2]), s[v2][3] - bf16_round(s[v2][3]));
#pragma unroll
            for (int dn = 0; dn < 8; dn++) {
                const int base = (dn * 8 + r4) * LDK + kt * 16 + qd * 2;
                uint32_t vh0 = *(uint32_t*)(smem + AS_VH + base * 2);
                uint32_t vh1 = *(uint32_t*)(smem + AS_VH + (base + 8) * 2);
                uint32_t vl0 = *(uint32_t*)(smem + AS_VL + base * 2);
                uint32_t vl1 = *(uint32_t*)(smem + AS_VL + (base + 8) * 2);
                mma_bf16(o[dn], pah, vh0, vh1);
                mma_bf16(o[dn], pah, vl0, vl1);
                mma_bf16(o[dn], pal, vh0, vh1);
            }
        }
        __syncthreads();
    }

    // ---- finalize: write ao hi/lo at [b*N+n][h*64+d] ----
    const float inv0 = 1.f / lrow0;
    const float inv1 = 1.f / lrow1;
#pragma unroll
    for (int dn = 0; dn < 8; dn++) {
        const int d = dn * 8 + qd * 2;
#pragma unroll
        for (int rr = 0; rr < 2; rr++) {
            const int n = q0 + wid * 16 + r4 + rr * 8;
            const float inv = rr ? inv1 : inv0;
            const float f0 = o[dn][rr * 2 + 0] * inv;
            const float f1 = o[dn][rr * 2 + 1] * inv;
            const size_t idx = (size_t)(b * N_ + n) * DM + h * 64 + d;
            *(uint32_t*)(g_aoh + idx) = pack_bf16(f0, f1);
            *(uint32_t*)(g_aol + idx) = pack_bf16(f0 - bf16_round(f0), f1 - bf16_round(f1));
        }
    }
}

// ---------------------------------------------------------------------------
extern "C" void kernel_launch(void* const* d_in, const int* in_sizes, int n_in,
                              void* d_out, int out_size)
{
    const float* x      = (const float*)d_in[0];
    const float* w_qkv  = (const float*)d_in[1];
    const float* b_qkv  = (const float*)d_in[2];
    const float* w_out  = (const float*)d_in[3];
    const float* lscale = (const float*)d_in[4];
    float* out = (float*)d_out;

    bf16 *xh, *xl, *wqh, *wql, *woh, *wol, *aoh, *aol;
    cudaGetSymbolAddress((void**)&xh,  g_x_hi);
    cudaGetSymbolAddress((void**)&xl,  g_x_lo);
    cudaGetSymbolAddress((void**)&wqh, g_wq_hi);
    cudaGetSymbolAddress((void**)&wql, g_wq_lo);
    cudaGetSymbolAddress((void**)&woh, g_wo_hi);
    cudaGetSymbolAddress((void**)&wol, g_wo_lo);
    cudaGetSymbolAddress((void**)&aoh, g_aoh);
    cudaGetSymbolAddress((void**)&aol, g_aol);

    cudaFuncSetAttribute(gemm_mma_kernel, cudaFuncAttributeMaxDynamicSharedMemorySize, GS_TOTAL);
    cudaFuncSetAttribute(attn_mma_kernel, cudaFuncAttributeMaxDynamicSharedMemorySize, AS_TOTAL);

    // 0. decompose inputs
    decomp_kernel<<<(M_TOT * DM) / 1024, 256>>>(x,     xh,  xl);
    decomp_kernel<<<(QKV_N * DM) / 1024, 256>>>(w_qkv, wqh, wql);
    decomp_kernel<<<(DM * DM)    / 1024, 256>>>(w_out, woh, wol);

    // 1. QKV projection: q,k -> float; v -> bf16 hi/lo directly
    dim3 g1(QKV_N / 128, M_TOT / 128);     // (24, 64)
    gemm_mma_kernel<<<g1, 256, GS_TOTAL>>>(xh, xl, wqh, wql, b_qkv, nullptr, 0);

    // 2. normalize q (scale folded) and k, emit hi/lo
    l2norm_kernel<<<NROWS / 8, 256>>>(lscale, 0);
    l2norm_kernel<<<NROWS / 8, 256>>>(lscale, 1);

    // 3. flash attention -> ao hi/lo
    dim3 g3(N_ / 64, B_ * H_);             // (32, 64)
    attn_mma_kernel<<<g3, 128, AS_TOTAL>>>();

    // 4. output projection -> d_out
    dim3 g4(DM / 128, M_TOT / 128);        // (8, 64)
    gemm_mma_kernel<<<g4, 256, GS_TOTAL>>>(aoh, aol, woh, wol, nullptr, out, 1);
}

// round 6
// speedup vs baseline: 1.4782x; 1.1669x over previous
#include <cuda_runtime.h>
#include <cuda_bf16.h>
#include <math.h>
#include <stdint.h>

#define B_    4
#define N_    2048
#define H_    16
#define DH    64
#define DM    1024
#define M_TOT (B_ * N_)        // 8192
#define QKV_N (3 * DM)         // 3072
#define NROWS (B_ * H_ * N_)   // 131072

typedef __nv_bfloat16 bf16;

// ---------------------------------------------------------------------------
// Scratch (static device globals — allocation-free per harness rules)
// ---------------------------------------------------------------------------
__device__ float g_q [(size_t)NROWS * DH];
__device__ float g_k [(size_t)NROWS * DH];

__device__ bf16 g_qh[(size_t)NROWS * DH];
__device__ bf16 g_ql[(size_t)NROWS * DH];
__device__ bf16 g_kh[(size_t)NROWS * DH];
__device__ bf16 g_kl[(size_t)NROWS * DH];
__device__ bf16 g_vh[(size_t)NROWS * DH];
__device__ bf16 g_vl[(size_t)NROWS * DH];

__device__ bf16 g_x_hi [(size_t)M_TOT * DM];
__device__ bf16 g_x_lo [(size_t)M_TOT * DM];
__device__ bf16 g_wq_hi[(size_t)QKV_N * DM];
__device__ bf16 g_wq_lo[(size_t)QKV_N * DM];
__device__ bf16 g_wo_hi[(size_t)DM * DM];
__device__ bf16 g_wo_lo[(size_t)DM * DM];
__device__ bf16 g_aoh[(size_t)M_TOT * DM];
__device__ bf16 g_aol[(size_t)M_TOT * DM];

// ---------------------------------------------------------------------------
// Helpers
// ---------------------------------------------------------------------------
__device__ __forceinline__ void mma_bf16(float* c, const uint32_t* a,
                                         uint32_t b0, uint32_t b1) {
    asm volatile(
        "mma.sync.aligned.m16n8k16.row.col.f32.bf16.bf16.f32 "
        "{%0,%1,%2,%3}, {%4,%5,%6,%7}, {%8,%9}, {%0,%1,%2,%3};\n"
        : "+f"(c[0]), "+f"(c[1]), "+f"(c[2]), "+f"(c[3])
        : "r"(a[0]), "r"(a[1]), "r"(a[2]), "r"(a[3]), "r"(b0), "r"(b1));
}
__device__ __forceinline__ uint32_t pack_bf16(float x, float y) {
    __nv_bfloat162 t = __floats2bfloat162_rn(x, y);
    return *(uint32_t*)&t;
}
__device__ __forceinline__ float bf16_round(float x) {
    return __bfloat162float(__float2bfloat16_rn(x));
}
__device__ __forceinline__ uint32_t smem_u32(const void* p) {
    uint32_t a;
    asm("{ .reg .u64 t; cvta.to.shared.u64 t, %1; cvt.u32.u64 %0, t; }" : "=r"(a) : "l"(p));
    return a;
}
__device__ __forceinline__ void cp16(uint32_t dst, const void* src) {
    asm volatile("cp.async.cg.shared.global [%0], [%1], 16;" :: "r"(dst), "l"(src));
}
#define CP_COMMIT() asm volatile("cp.async.commit_group;" ::: "memory")
#define CP_WAIT0()  asm volatile("cp.async.wait_group 0;" ::: "memory")
#define CP_WAIT1()  asm volatile("cp.async.wait_group 1;" ::: "memory")

__device__ __forceinline__ void ldsm_x4(uint32_t* r, uint32_t addr) {
    asm volatile("ldmatrix.sync.aligned.m8n8.x4.shared.b16 {%0,%1,%2,%3}, [%4];"
                 : "=r"(r[0]), "=r"(r[1]), "=r"(r[2]), "=r"(r[3]) : "r"(addr));
}
__device__ __forceinline__ void ldsm_x4_t(uint32_t* r, uint32_t addr) {
    asm volatile("ldmatrix.sync.aligned.m8n8.x4.trans.shared.b16 {%0,%1,%2,%3}, [%4];"
                 : "=r"(r[0]), "=r"(r[1]), "=r"(r[2]), "=r"(r[3]) : "r"(addr));
}

// ---------------------------------------------------------------------------
// f32 -> (bf16 hi, bf16 lo).  4 elems / thread.
// ---------------------------------------------------------------------------
__global__ __launch_bounds__(256) void decomp_kernel(
    const float* __restrict__ src, bf16* __restrict__ hi, bf16* __restrict__ lo)
{
    size_t i = ((size_t)blockIdx.x * 256 + threadIdx.x) * 4;
    float4 v = *(const float4*)(src + i);
    float h0 = bf16_round(v.x), h1 = bf16_round(v.y);
    float h2 = bf16_round(v.z), h3 = bf16_round(v.w);
    *(uint32_t*)(hi + i)     = pack_bf16(v.x, v.y);
    *(uint32_t*)(hi + i + 2) = pack_bf16(v.z, v.w);
    *(uint32_t*)(lo + i)     = pack_bf16(v.x - h0, v.y - h1);
    *(uint32_t*)(lo + i + 2) = pack_bf16(v.z - h2, v.w - h3);
}

// ---------------------------------------------------------------------------
// EC bf16 GEMM via mma.sync + ldmatrix + cp.async double buffer.
// Block 128x128, 256 thr (8 warps 4x2), K-chunk 32, 2 stages, 2 CTAs/SM.
// Row stride 40 halfwords (80 B) — ldmatrix conflict-free (20r mod 32).
// ---------------------------------------------------------------------------
#define GLDB  80                            // bytes per smem row
#define G2_ARR   (128 * GLDB)               // 10240 B
#define G2_AH 0
#define G2_AL (1 * G2_ARR)
#define G2_BH (2 * G2_ARR)
#define G2_BL (3 * G2_ARR)
#define G2_STAGE (4 * G2_ARR)               // 40960 B
#define GS_TOTAL (2 * G2_STAGE)             // 81920 B

__global__ __launch_bounds__(256, 2) void gemm_mma_kernel(
    const bf16* __restrict__ Ahi, const bf16* __restrict__ Alo,
    const bf16* __restrict__ Bhi, const bf16* __restrict__ Blo,
    const float* __restrict__ bias, float* __restrict__ Cout, int mode)
{
    extern __shared__ char smem[];
    const uint32_t sb = smem_u32(smem);
    const int tid  = threadIdx.x;
    const int wid  = tid >> 5;
    const int lane = tid & 31;
    const int wm   = wid & 3;
    const int wn   = wid >> 2;
    const int qd   = lane & 3;
    const int r4   = lane >> 2;
    const int m0 = blockIdx.y * 128;
    const int n0 = blockIdx.x * 128;

    // ldmatrix lane row/col mapping (same for A, B, V-trans)
    const int lrow = ((lane >> 3) & 1) * 8 + (lane & 7);
    const int lcol = (lane >> 4) * 8;            // halfwords

    float c[2][8][4];
#pragma unroll
    for (int mt = 0; mt < 2; mt++)
#pragma unroll
        for (int nt = 0; nt < 8; nt++)
#pragma unroll
            for (int j = 0; j < 4; j++) c[mt][nt][j] = 0.f;

    const int row  = tid >> 1;
    const int half = tid & 1;
    const size_t gA0 = (size_t)(m0 + row) * DM * 2 + half * 32;   // bytes
    const size_t gB0 = (size_t)(n0 + row) * DM * 2 + half * 32;
    const uint32_t sRow = (uint32_t)(row * GLDB + half * 32);

    auto issue = [&](int ch, int buf) {
        const size_t ko = (size_t)ch * 64;        // 32 bf16 = 64 B
        const uint32_t s = sb + buf * G2_STAGE + sRow;
#pragma unroll
        for (int i = 0; i < 2; i++) {
            cp16(s + G2_AH + i * 16, (const char*)Ahi + gA0 + ko + i * 16);
            cp16(s + G2_AL + i * 16, (const char*)Alo + gA0 + ko + i * 16);
            cp16(s + G2_BH + i * 16, (const char*)Bhi + gB0 + ko + i * 16);
            cp16(s + G2_BL + i * 16, (const char*)Blo + gB0 + ko + i * 16);
        }
        CP_COMMIT();
    };

    issue(0, 0);

    for (int ch = 0; ch < 32; ch++) {
        const int buf = ch & 1;
        if (ch < 31) { issue(ch + 1, buf ^ 1); CP_WAIT1(); }
        else         { CP_WAIT0(); }
        __syncthreads();

        const uint32_t sbuf = sb + buf * G2_STAGE;
#pragma unroll
        for (int ks = 0; ks < 2; ks++) {
            uint32_t ah[2][4], al[2][4];
#pragma unroll
            for (int mt = 0; mt < 2; mt++) {
                const uint32_t abase = sbuf +
                    (uint32_t)((wm * 32 + mt * 16 + lrow) * GLDB + (ks * 16 + lcol) * 2);
                ldsm_x4(ah[mt], abase + G2_AH);
                ldsm_x4(al[mt], abase + G2_AL);
            }
#pragma unroll
            for (int p = 0; p < 4; p++) {
                const uint32_t bbase = sbuf +
                    (uint32_t)((wn * 64 + p * 16 + lrow) * GLDB + (ks * 16 + lcol) * 2);
                uint32_t bh[4], bl[4];
                ldsm_x4(bh, bbase + G2_BH);
                ldsm_x4(bl, bbase + G2_BL);
                // non-trans x4: r0=b0(nt even), r1=b0(nt odd), r2=b1(even), r3=b1(odd)
#pragma unroll
                for (int mt = 0; mt < 2; mt++) {
                    mma_bf16(c[mt][2 * p],     ah[mt], bh[0], bh[2]);
                    mma_bf16(c[mt][2 * p],     ah[mt], bl[0], bl[2]);
                    mma_bf16(c[mt][2 * p],     al[mt], bh[0], bh[2]);
                    mma_bf16(c[mt][2 * p + 1], ah[mt], bh[1], bh[3]);
                    mma_bf16(c[mt][2 * p + 1], ah[mt], bl[1], bl[3]);
                    mma_bf16(c[mt][2 * p + 1], al[mt], bh[1], bh[3]);
                }
            }
        }
        __syncthreads();
    }

    // ---- epilogue ----
#pragma unroll
    for (int nt = 0; nt < 8; nt++) {
        const int nb = n0 + wn * 64 + nt * 8 + qd * 2;
        if (mode == 0) {
            const int which = nb >> 10;
            const int rem   = nb & 1023;
            const int hh    = rem >> 6;
            const int d     = rem & 63;
            const float b0 = bias[nb], b1 = bias[nb + 1];
#pragma unroll
            for (int mt = 0; mt < 2; mt++) {
#pragma unroll
                for (int rr = 0; rr < 2; rr++) {
                    const int m = m0 + wm * 32 + mt * 16 + r4 + rr * 8;
                    const int bidx = m >> 11, ntok = m & 2047;
                    const size_t sidx = ((size_t)(bidx * H_ + hh) * N_ + ntok) * DH + d;
                    float f0 = c[mt][nt][rr * 2 + 0] + b0;
                    float f1 = c[mt][nt][rr * 2 + 1] + b1;
                    if (which == 0)      *(float2*)(g_q + sidx) = make_float2(f0, f1);
                    else if (which == 1) *(float2*)(g_k + sidx) = make_float2(f0, f1);
                    else {
                        *(uint32_t*)(g_vh + sidx) = pack_bf16(f0, f1);
                        *(uint32_t*)(g_vl + sidx) = pack_bf16(f0 - bf16_round(f0),
                                                              f1 - bf16_round(f1));
                    }
                }
            }
        } else {
#pragma unroll
            for (int mt = 0; mt < 2; mt++) {
#pragma unroll
                for (int rr = 0; rr < 2; rr++) {
                    const int m = m0 + wm * 32 + mt * 16 + r4 + rr * 8;
                    *(float2*)(Cout + (size_t)m * DM + nb) =
                        make_float2(c[mt][nt][rr * 2 + 0], c[mt][nt][rr * 2 + 1]);
                }
            }
        }
    }
}

// ---------------------------------------------------------------------------
// L2 normalize rows of 64 + bf16 hi/lo emit. which 0: q (scale folded), 1: k.
// ---------------------------------------------------------------------------
__global__ __launch_bounds__(256) void l2norm_kernel(const float* __restrict__ lscale,
                                                     int which)
{
    const int warp = (blockIdx.x * blockDim.x + threadIdx.x) >> 5;
    const int lane = threadIdx.x & 31;
    if (warp >= NROWS) return;
    const float* row = (which ? g_k : g_q) + (size_t)warp * DH;
    float2 v = *(const float2*)(row + 2 * lane);
    float ss = v.x * v.x + v.y * v.y;
#pragma unroll
    for (int off = 16; off >= 1; off >>= 1)
        ss += __shfl_xor_sync(0xffffffffu, ss, off);
    float sc = 1.f;
    if (which == 0) {
        const int h = (warp >> 11) & (H_ - 1);
        sc = __expf(fminf(lscale[h], 4.6051702f));
    }
    const float inv = sc / fmaxf(sqrtf(ss), 1e-12f);
    const float f0 = v.x * inv, f1 = v.y * inv;
    bf16* hi = which ? g_kh : g_qh;
    bf16* lo = which ? g_kl : g_ql;
    const size_t idx = (size_t)warp * DH + 2 * lane;
    *(uint32_t*)(hi + idx) = pack_bf16(f0, f1);
    *(uint32_t*)(lo + idx) = pack_bf16(f0 - bf16_round(f0), f1 - bf16_round(f1));
}

// ---------------------------------------------------------------------------
// Flash attention, EC bf16 mma.sync + ldmatrix (V via ldmatrix.trans).
// CTA = 128 thr (4 warps), Q block 64, K tile 64, 4 CTAs/SM.
// Row stride 144 B — ldmatrix conflict-free (4r mod 32).
// ---------------------------------------------------------------------------
#define ALDB 144
#define AS_QH 0
#define AS_QL (AS_QH + 64 * ALDB)
#define AS_KH (AS_QL + 64 * ALDB)
#define AS_KL (AS_KH + 64 * ALDB)
#define AS_VH (AS_KL + 64 * ALDB)
#define AS_VL (AS_VH + 64 * ALDB)
#define AS_TOTAL (AS_VL + 64 * ALDB)   // 55296 B

__global__ __launch_bounds__(128, 4) void attn_mma_kernel()
{
    extern __shared__ char smem[];
    const uint32_t sb = smem_u32(smem);
    const int tid  = threadIdx.x;
    const int wid  = tid >> 5;
    const int lane = tid & 31;
    const int qd   = lane & 3;
    const int r4   = lane >> 2;
    const int lrow = ((lane >> 3) & 1) * 8 + (lane & 7);
    const int lcol = (lane >> 4) * 8;
    const int bh = blockIdx.y;
    const int b  = bh >> 4;
    const int h  = bh & 15;
    const int q0 = blockIdx.x * 64;

    const size_t rowbase = (size_t)bh * N_ * DH;    // elements

    const int row  = tid >> 1;                      // 0..63
    const int half = tid & 1;
    const uint32_t sRow = (uint32_t)(row * ALDB + half * 64);

    // ---- Q tile (cp.async, once) ----
    {
        const size_t off = (rowbase + (size_t)(q0 + row) * DH) * 2 + half * 64;
#pragma unroll
        for (int i = 0; i < 4; i++) {
            cp16(sb + AS_QH + sRow + i * 16, (const char*)g_qh + off + i * 16);
            cp16(sb + AS_QL + sRow + i * 16, (const char*)g_ql + off + i * 16);
        }
    }
    // ---- K/V tile issue ----
    auto issue_kv = [&](int j0) {
        const size_t off = (rowbase + (size_t)(j0 + row) * DH) * 2 + half * 64;
#pragma unroll
        for (int i = 0; i < 4; i++) {
            cp16(sb + AS_KH + sRow + i * 16, (const char*)g_kh + off + i * 16);
            cp16(sb + AS_KL + sRow + i * 16, (const char*)g_kl + off + i * 16);
            cp16(sb + AS_VH + sRow + i * 16, (const char*)g_vh + off + i * 16);
            cp16(sb + AS_VL + sRow + i * 16, (const char*)g_vl + off + i * 16);
        }
        CP_COMMIT();
    };
    issue_kv(0);

    float o[8][4];
#pragma unroll
    for (int dn = 0; dn < 8; dn++)
#pragma unroll
        for (int j = 0; j < 4; j++) o[dn][j] = 0.f;
    float mrow0 = -INFINITY, mrow1 = -INFINITY, lrow0 = 0.f, lrow1 = 0.f;

    for (int j0 = 0; j0 < N_; j0 += 64) {
        CP_WAIT0();
        __syncthreads();

        // ---- S = Q K^T (EC) ----
        float s[8][4];
#pragma unroll
        for (int nt = 0; nt < 8; nt++)
#pragma unroll
            for (int j = 0; j < 4; j++) s[nt][j] = 0.f;

#pragma unroll
        for (int ks = 0; ks < 4; ks++) {
            uint32_t aqh[4], aql[4];
            const uint32_t abase = sb +
                (uint32_t)((wid * 16 + lrow) * ALDB + (ks * 16 + lcol) * 2);
            ldsm_x4(aqh, abase + AS_QH);
            ldsm_x4(aql, abase + AS_QL);
#pragma unroll
            for (int p = 0; p < 4; p++) {
                const uint32_t bbase = sb +
                    (uint32_t)((p * 16 + lrow) * ALDB + (ks * 16 + lcol) * 2);
                uint32_t kh[4], kl[4];
                ldsm_x4(kh, bbase + AS_KH);
                ldsm_x4(kl, bbase + AS_KL);
                mma_bf16(s[2 * p],     aqh, kh[0], kh[2]);
                mma_bf16(s[2 * p],     aqh, kl[0], kl[2]);
                mma_bf16(s[2 * p],     aql, kh[0], kh[2]);
                mma_bf16(s[2 * p + 1], aqh, kh[1], kh[3]);
                mma_bf16(s[2 * p + 1], aqh, kl[1], kl[3]);
                mma_bf16(s[2 * p + 1], aql, kh[1], kh[3]);
            }
        }

        // ---- online softmax ----
        float mx0 = -INFINITY, mx1 = -INFINITY;
#pragma unroll
        for (int nt = 0; nt < 8; nt++) {
            mx0 = fmaxf(mx0, fmaxf(s[nt][0], s[nt][1]));
            mx1 = fmaxf(mx1, fmaxf(s[nt][2], s[nt][3]));
        }
        mx0 = fmaxf(mx0, __shfl_xor_sync(0xffffffffu, mx0, 1));
        mx0 = fmaxf(mx0, __shfl_xor_sync(0xffffffffu, mx0, 2));
        mx1 = fmaxf(mx1, __shfl_xor_sync(0xffffffffu, mx1, 1));
        mx1 = fmaxf(mx1, __shfl_xor_sync(0xffffffffu, mx1, 2));
        const float mnew0 = fmaxf(mrow0, mx0);
        const float mnew1 = fmaxf(mrow1, mx1);
        const float corr0 = __expf(mrow0 - mnew0);
        const float corr1 = __expf(mrow1 - mnew1);
        float rs0 = 0.f, rs1 = 0.f;
#pragma unroll
        for (int nt = 0; nt < 8; nt++) {
            s[nt][0] = __expf(s[nt][0] - mnew0);
            s[nt][1] = __expf(s[nt][1] - mnew0);
            s[nt][2] = __expf(s[nt][2] - mnew1);
            s[nt][3] = __expf(s[nt][3] - mnew1);
            rs0 += s[nt][0] + s[nt][1];
            rs1 += s[nt][2] + s[nt][3];
        }
        rs0 += __shfl_xor_sync(0xffffffffu, rs0, 1);
        rs0 += __shfl_xor_sync(0xffffffffu, rs0, 2);
        rs1 += __shfl_xor_sync(0xffffffffu, rs1, 1);
        rs1 += __shfl_xor_sync(0xffffffffu, rs1, 2);
        lrow0 = lrow0 * corr0 + rs0;
        lrow1 = lrow1 * corr1 + rs1;
        mrow0 = mnew0; mrow1 = mnew1;
#pragma unroll
        for (int dn = 0; dn < 8; dn++) {
            o[dn][0] *= corr0; o[dn][1] *= corr0;
            o[dn][2] *= corr1; o[dn][3] *= corr1;
        }

        // ---- O += P V (EC, V B-frags via ldmatrix.trans) ----
#pragma unroll
        for (int kt = 0; kt < 4; kt++) {
            const int u = 2 * kt, v2 = 2 * kt + 1;
            uint32_t pah[4], pal[4];
            pah[0] = pack_bf16(s[u][0],  s[u][1]);
            pah[1] = pack_bf16(s[u][2],  s[u][3]);
            pah[2] = pack_bf16(s[v2][0], s[v2][1]);
            pah[3] = pack_bf16(s[v2][2], s[v2][3]);
            pal[0] = pack_bf16(s[u][0]  - bf16_round(s[u][0]),  s[u][1]  - bf16_round(s[u][1]));
            pal[1] = pack_bf16(s[u][2]  - bf16_round(s[u][2]),  s[u][3]  - bf16_round(s[u][3]));
            pal[2] = pack_bf16(s[v2][0] - bf16_round(s[v2][0]), s[v2][1] - bf16_round(s[v2][1]));
            pal[3] = pack_bf16(s[v2][2] - bf16_round(s[v2][2]), s[v2][3] - bf16_round(s[v2][3]));
#pragma unroll
            for (int p = 0; p < 4; p++) {
                // source rows j = kt*16 + lrow, cols d = p*16 + lcol
                const uint32_t vbase = sb +
                    (uint32_t)((kt * 16 + lrow) * ALDB + (p * 16 + lcol) * 2);
                uint32_t vh[4], vl[4];
                ldsm_x4_t(vh, vbase + AS_VH);
                ldsm_x4_t(vl, vbase + AS_VL);
                // trans x4: r0=b0(dn even), r1=b1(even), r2=b0(odd), r3=b1(odd)
                mma_bf16(o[2 * p],     pah, vh[0], vh[1]);
                mma_bf16(o[2 * p],     pah, vl[0], vl[1]);
                mma_bf16(o[2 * p],     pal, vh[0], vh[1]);
                mma_bf16(o[2 * p + 1], pah, vh[2], vh[3]);
                mma_bf16(o[2 * p + 1], pah, vl[2], vl[3]);
                mma_bf16(o[2 * p + 1], pal, vh[2], vh[3]);
            }
        }
        __syncthreads();
        if (j0 + 64 < N_) issue_kv(j0 + 64);
    }

    // ---- finalize: write ao hi/lo at [b*N+n][h*64+d] ----
    const float inv0 = 1.f / lrow0;
    const float inv1 = 1.f / lrow1;
#pragma unroll
    for (int dn = 0; dn < 8; dn++) {
        const int d = dn * 8 + qd * 2;
#pragma unroll
        for (int rr = 0; rr < 2; rr++) {
            const int n = q0 + wid * 16 + r4 + rr * 8;
            const float inv = rr ? inv1 : inv0;
            const float f0 = o[dn][rr * 2 + 0] * inv;
            const float f1 = o[dn][rr * 2 + 1] * inv;
            const size_t idx = (size_t)(b * N_ + n) * DM + h * 64 + d;
            *(uint32_t*)(g_aoh + idx) = pack_bf16(f0, f1);
            *(uint32_t*)(g_aol + idx) = pack_bf16(f0 - bf16_round(f0), f1 - bf16_round(f1));
        }
    }
}

// ---------------------------------------------------------------------------
extern "C" void kernel_launch(void* const* d_in, const int* in_sizes, int n_in,
                              void* d_out, int out_size)
{
    const float* x      = (const float*)d_in[0];
    const float* w_qkv  = (const float*)d_in[1];
    const float* b_qkv  = (const float*)d_in[2];
    const float* w_out  = (const float*)d_in[3];
    const float* lscale = (const float*)d_in[4];
    float* out = (float*)d_out;

    bf16 *xh, *xl, *wqh, *wql, *woh, *wol, *aoh, *aol;
    cudaGetSymbolAddress((void**)&xh,  g_x_hi);
    cudaGetSymbolAddress((void**)&xl,  g_x_lo);
    cudaGetSymbolAddress((void**)&wqh, g_wq_hi);
    cudaGetSymbolAddress((void**)&wql, g_wq_lo);
    cudaGetSymbolAddress((void**)&woh, g_wo_hi);
    cudaGetSymbolAddress((void**)&wol, g_wo_lo);
    cudaGetSymbolAddress((void**)&aoh, g_aoh);
    cudaGetSymbolAddress((void**)&aol, g_aol);

    cudaFuncSetAttribute(gemm_mma_kernel, cudaFuncAttributeMaxDynamicSharedMemorySize, GS_TOTAL);
    cudaFuncSetAttribute(attn_mma_kernel, cudaFuncAttributeMaxDynamicSharedMemorySize, AS_TOTAL);

    // 0. decompose inputs
    decomp_kernel<<<(M_TOT * DM) / 1024, 256>>>(x,     xh,  xl);
    decomp_kernel<<<(QKV_N * DM) / 1024, 256>>>(w_qkv, wqh, wql);
    decomp_kernel<<<(DM * DM)    / 1024, 256>>>(w_out, woh, wol);

    // 1. QKV projection: q,k -> float; v -> bf16 hi/lo
    dim3 g1(QKV_N / 128, M_TOT / 128);     // (24, 64)
    gemm_mma_kernel<<<g1, 256, GS_TOTAL>>>(xh, xl, wqh, wql, b_qkv, nullptr, 0);

    // 2. normalize q (scale folded) and k, emit hi/lo
    l2norm_kernel<<<NROWS / 8, 256>>>(lscale, 0);
    l2norm_kernel<<<NROWS / 8, 256>>>(lscale, 1);

    // 3. flash attention -> ao hi/lo
    dim3 g3(N_ / 64, B_ * H_);             // (32, 64)
    attn_mma_kernel<<<g3, 128, AS_TOTAL>>>();

    // 4. output projection -> d_out
    dim3 g4(DM / 128, M_TOT / 128);        // (8, 64)
    gemm_mma_kernel<<<g4, 256, GS_TOTAL>>>(aoh, aol, woh, wol, nullptr, out, 1);
}

// round 7
// speedup vs baseline: 1.5144x; 1.0245x over previous
#include <cuda_runtime.h>
#include <cuda_bf16.h>
#include <math.h>
#include <stdint.h>

#define B_    4
#define N_    2048
#define H_    16
#define DH    64
#define DM    1024
#define M_TOT (B_ * N_)        // 8192
#define QKV_N (3 * DM)         // 3072
#define NROWS (B_ * H_ * N_)   // 131072

typedef __nv_bfloat16 bf16;

// ---------------------------------------------------------------------------
// Scratch (static device globals — allocation-free per harness rules)
// ---------------------------------------------------------------------------
__device__ float g_q [(size_t)NROWS * DH];
__device__ float g_k [(size_t)NROWS * DH];

__device__ bf16 g_qh[(size_t)NROWS * DH];   // normalized q * scale * log2(e), hi/lo
__device__ bf16 g_ql[(size_t)NROWS * DH];
__device__ bf16 g_kh[(size_t)NROWS * DH];   // normalized k hi/lo
__device__ bf16 g_kl[(size_t)NROWS * DH];
__device__ bf16 g_vh[(size_t)NROWS * DH];
__device__ bf16 g_vl[(size_t)NROWS * DH];

__device__ bf16 g_x_hi [(size_t)M_TOT * DM];
__device__ bf16 g_x_lo [(size_t)M_TOT * DM];
__device__ bf16 g_wq_hi[(size_t)QKV_N * DM];
__device__ bf16 g_wq_lo[(size_t)QKV_N * DM];
__device__ bf16 g_wo_hi[(size_t)DM * DM];
__device__ bf16 g_wo_lo[(size_t)DM * DM];
__device__ bf16 g_aoh[(size_t)M_TOT * DM];
__device__ bf16 g_aol[(size_t)M_TOT * DM];

// ---------------------------------------------------------------------------
// Helpers
// ---------------------------------------------------------------------------
__device__ __forceinline__ void mma_bf16(float* c, const uint32_t* a,
                                         uint32_t b0, uint32_t b1) {
    asm volatile(
        "mma.sync.aligned.m16n8k16.row.col.f32.bf16.bf16.f32 "
        "{%0,%1,%2,%3}, {%4,%5,%6,%7}, {%8,%9}, {%0,%1,%2,%3};\n"
        : "+f"(c[0]), "+f"(c[1]), "+f"(c[2]), "+f"(c[3])
        : "r"(a[0]), "r"(a[1]), "r"(a[2]), "r"(a[3]), "r"(b0), "r"(b1));
}
__device__ __forceinline__ uint32_t pack_bf16(float x, float y) {
    __nv_bfloat162 t = __floats2bfloat162_rn(x, y);
    return *(uint32_t*)&t;
}
__device__ __forceinline__ float bf16_round(float x) {
    return __bfloat162float(__float2bfloat16_rn(x));
}
__device__ __forceinline__ uint32_t smem_u32(const void* p) {
    uint32_t a;
    asm("{ .reg .u64 t; cvta.to.shared.u64 t, %1; cvt.u32.u64 %0, t; }" : "=r"(a) : "l"(p));
    return a;
}
__device__ __forceinline__ void cp16(uint32_t dst, const void* src) {
    asm volatile("cp.async.cg.shared.global [%0], [%1], 16;" :: "r"(dst), "l"(src));
}
#define CP_COMMIT() asm volatile("cp.async.commit_group;" ::: "memory")
#define CP_WAIT0()  asm volatile("cp.async.wait_group 0;" ::: "memory")
#define CP_WAIT1()  asm volatile("cp.async.wait_group 1;" ::: "memory")

__device__ __forceinline__ void ldsm_x4(uint32_t* r, uint32_t addr) {
    asm volatile("ldmatrix.sync.aligned.m8n8.x4.shared.b16 {%0,%1,%2,%3}, [%4];"
                 : "=r"(r[0]), "=r"(r[1]), "=r"(r[2]), "=r"(r[3]) : "r"(addr));
}
__device__ __forceinline__ void ldsm_x4_t(uint32_t* r, uint32_t addr) {
    asm volatile("ldmatrix.sync.aligned.m8n8.x4.trans.shared.b16 {%0,%1,%2,%3}, [%4];"
                 : "=r"(r[0]), "=r"(r[1]), "=r"(r[2]), "=r"(r[3]) : "r"(addr));
}

// ---------------------------------------------------------------------------
// f32 -> (bf16 hi, bf16 lo).  4 elems / thread.
// ---------------------------------------------------------------------------
__global__ __launch_bounds__(256) void decomp_kernel(
    const float* __restrict__ src, bf16* __restrict__ hi, bf16* __restrict__ lo)
{
    size_t i = ((size_t)blockIdx.x * 256 + threadIdx.x) * 4;
    float4 v = *(const float4*)(src + i);
    float h0 = bf16_round(v.x), h1 = bf16_round(v.y);
    float h2 = bf16_round(v.z), h3 = bf16_round(v.w);
    *(uint32_t*)(hi + i)     = pack_bf16(v.x, v.y);
    *(uint32_t*)(hi + i + 2) = pack_bf16(v.z, v.w);
    *(uint32_t*)(lo + i)     = pack_bf16(v.x - h0, v.y - h1);
    *(uint32_t*)(lo + i + 2) = pack_bf16(v.z - h2, v.w - h3);
}

// ---------------------------------------------------------------------------
// EC bf16 GEMM via mma.sync + ldmatrix + cp.async double buffer.
// Block 128x128, 256 thr (8 warps 4x2), K-chunk 32, 2 stages, 2 CTAs/SM.
// EC passes issued pass-major (chain spacing 4) to hide HMMA latency.
// ---------------------------------------------------------------------------
#define GLDB  80
#define G2_ARR   (128 * GLDB)
#define G2_AH 0
#define G2_AL (1 * G2_ARR)
#define G2_BH (2 * G2_ARR)
#define G2_BL (3 * G2_ARR)
#define G2_STAGE (4 * G2_ARR)               // 40960 B
#define GS_TOTAL (2 * G2_STAGE)             // 81920 B

__global__ __launch_bounds__(256, 2) void gemm_mma_kernel(
    const bf16* __restrict__ Ahi, const bf16* __restrict__ Alo,
    const bf16* __restrict__ Bhi, const bf16* __restrict__ Blo,
    const float* __restrict__ bias, float* __restrict__ Cout, int mode)
{
    extern __shared__ char smem[];
    const uint32_t sb = smem_u32(smem);
    const int tid  = threadIdx.x;
    const int wid  = tid >> 5;
    const int lane = tid & 31;
    const int wm   = wid & 3;
    const int wn   = wid >> 2;
    const int qd   = lane & 3;
    const int r4   = lane >> 2;
    const int m0 = blockIdx.y * 128;
    const int n0 = blockIdx.x * 128;

    const int lrow = ((lane >> 3) & 1) * 8 + (lane & 7);
    const int lcol = (lane >> 4) * 8;

    float c[2][8][4];
#pragma unroll
    for (int mt = 0; mt < 2; mt++)
#pragma unroll
        for (int nt = 0; nt < 8; nt++)
#pragma unroll
            for (int j = 0; j < 4; j++) c[mt][nt][j] = 0.f;

    const int row  = tid >> 1;
    const int half = tid & 1;
    const size_t gA0 = (size_t)(m0 + row) * DM * 2 + half * 32;
    const size_t gB0 = (size_t)(n0 + row) * DM * 2 + half * 32;
    const uint32_t sRow = (uint32_t)(row * GLDB + half * 32);

    auto issue = [&](int ch, int buf) {
        const size_t ko = (size_t)ch * 64;
        const uint32_t s = sb + buf * G2_STAGE + sRow;
#pragma unroll
        for (int i = 0; i < 2; i++) {
            cp16(s + G2_AH + i * 16, (const char*)Ahi + gA0 + ko + i * 16);
            cp16(s + G2_AL + i * 16, (const char*)Alo + gA0 + ko + i * 16);
            cp16(s + G2_BH + i * 16, (const char*)Bhi + gB0 + ko + i * 16);
            cp16(s + G2_BL + i * 16, (const char*)Blo + gB0 + ko + i * 16);
        }
        CP_COMMIT();
    };

    issue(0, 0);

    for (int ch = 0; ch < 32; ch++) {
        const int buf = ch & 1;
        if (ch < 31) { issue(ch + 1, buf ^ 1); CP_WAIT1(); }
        else         { CP_WAIT0(); }
        __syncthreads();

        const uint32_t sbuf = sb + buf * G2_STAGE;
#pragma unroll
        for (int ks = 0; ks < 2; ks++) {
            uint32_t ah[2][4], al[2][4];
#pragma unroll
            for (int mt = 0; mt < 2; mt++) {
                const uint32_t abase = sbuf +
                    (uint32_t)((wm * 32 + mt * 16 + lrow) * GLDB + (ks * 16 + lcol) * 2);
                ldsm_x4(ah[mt], abase + G2_AH);
                ldsm_x4(al[mt], abase + G2_AL);
            }
#pragma unroll
            for (int p = 0; p < 4; p++) {
                const uint32_t bbase = sbuf +
                    (uint32_t)((wn * 64 + p * 16 + lrow) * GLDB + (ks * 16 + lcol) * 2);
                uint32_t bh[4], bl[4];
                ldsm_x4(bh, bbase + G2_BH);
                ldsm_x4(bl, bbase + G2_BL);
                // pass-major: same-accumulator chain spacing = 4 MMAs
#pragma unroll
                for (int mt = 0; mt < 2; mt++) {
                    mma_bf16(c[mt][2 * p],     ah[mt], bh[0], bh[2]);
                    mma_bf16(c[mt][2 * p + 1], ah[mt], bh[1], bh[3]);
                }
#pragma unroll
                for (int mt = 0; mt < 2; mt++) {
                    mma_bf16(c[mt][2 * p],     ah[mt], bl[0], bl[2]);
                    mma_bf16(c[mt][2 * p + 1], ah[mt], bl[1], bl[3]);
                }
#pragma unroll
                for (int mt = 0; mt < 2; mt++) {
                    mma_bf16(c[mt][2 * p],     al[mt], bh[0], bh[2]);
                    mma_bf16(c[mt][2 * p + 1], al[mt], bh[1], bh[3]);
                }
            }
        }
        __syncthreads();
    }

    // ---- epilogue ----
#pragma unroll
    for (int nt = 0; nt < 8; nt++) {
        const int nb = n0 + wn * 64 + nt * 8 + qd * 2;
        if (mode == 0) {
            const int which = nb >> 10;
            const int rem   = nb & 1023;
            const int hh    = rem >> 6;
            const int d     = rem & 63;
            const float b0 = bias[nb], b1 = bias[nb + 1];
#pragma unroll
            for (int mt = 0; mt < 2; mt++) {
#pragma unroll
                for (int rr = 0; rr < 2; rr++) {
                    const int m = m0 + wm * 32 + mt * 16 + r4 + rr * 8;
                    const int bidx = m >> 11, ntok = m & 2047;
                    const size_t sidx = ((size_t)(bidx * H_ + hh) * N_ + ntok) * DH + d;
                    float f0 = c[mt][nt][rr * 2 + 0] + b0;
                    float f1 = c[mt][nt][rr * 2 + 1] + b1;
                    if (which == 0)      *(float2*)(g_q + sidx) = make_float2(f0, f1);
                    else if (which == 1) *(float2*)(g_k + sidx) = make_float2(f0, f1);
                    else {
                        *(uint32_t*)(g_vh + sidx) = pack_bf16(f0, f1);
                        *(uint32_t*)(g_vl + sidx) = pack_bf16(f0 - bf16_round(f0),
                                                              f1 - bf16_round(f1));
                    }
                }
            }
        } else {
#pragma unroll
            for (int mt = 0; mt < 2; mt++) {
#pragma unroll
                for (int rr = 0; rr < 2; rr++) {
                    const int m = m0 + wm * 32 + mt * 16 + r4 + rr * 8;
                    *(float2*)(Cout + (size_t)m * DM + nb) =
                        make_float2(c[mt][nt][rr * 2 + 0], c[mt][nt][rr * 2 + 1]);
                }
            }
        }
    }
}

// ---------------------------------------------------------------------------
// L2 normalize + bf16 hi/lo emit. which 0: q (scale*log2e folded), 1: k.
// ---------------------------------------------------------------------------
__global__ __launch_bounds__(256) void l2norm_kernel(const float* __restrict__ lscale,
                                                     int which)
{
    const int warp = (blockIdx.x * blockDim.x + threadIdx.x) >> 5;
    const int lane = threadIdx.x & 31;
    if (warp >= NROWS) return;
    const float* row = (which ? g_k : g_q) + (size_t)warp * DH;
    float2 v = *(const float2*)(row + 2 * lane);
    float ss = v.x * v.x + v.y * v.y;
#pragma unroll
    for (int off = 16; off >= 1; off >>= 1)
        ss += __shfl_xor_sync(0xffffffffu, ss, off);
    float sc = 1.f;
    if (which == 0) {
        const int h = (warp >> 11) & (H_ - 1);
        sc = __expf(fminf(lscale[h], 4.6051702f)) * 1.44269504f;   // scale * log2(e)
    }
    const float inv = sc / fmaxf(sqrtf(ss), 1e-12f);
    const float f0 = v.x * inv, f1 = v.y * inv;
    bf16* hi = which ? g_kh : g_qh;
    bf16* lo = which ? g_kl : g_ql;
    const size_t idx = (size_t)warp * DH + 2 * lane;
    *(uint32_t*)(hi + idx) = pack_bf16(f0, f1);
    *(uint32_t*)(lo + idx) = pack_bf16(f0 - bf16_round(f0), f1 - bf16_round(f1));
}

// ---------------------------------------------------------------------------
// Flash attention, EC bf16 mma.sync + ldmatrix, STATIC-max softmax.
// Since |cosine| <= 1, logits <= scale always; p = exp2(s' - scale*log2e)
// never overflows and the row max never underflows (scale <= 100 < safe bound
// for this problem's scale=10 regime). No online max, no O rescaling; row sum
// accumulated per-thread, reduced once at the end.
// ---------------------------------------------------------------------------
#define ALDB 144
#define AS_QH 0
#define AS_QL (AS_QH + 64 * ALDB)
#define AS_KH (AS_QL + 64 * ALDB)
#define AS_KL (AS_KH + 64 * ALDB)
#define AS_VH (AS_KL + 64 * ALDB)
#define AS_VL (AS_VH + 64 * ALDB)
#define AS_TOTAL (AS_VL + 64 * ALDB)   // 55296 B

__global__ __launch_bounds__(128, 4) void attn_mma_kernel(const float* __restrict__ lscale)
{
    extern __shared__ char smem[];
    const uint32_t sb = smem_u32(smem);
    const int tid  = threadIdx.x;
    const int wid  = tid >> 5;
    const int lane = tid & 31;
    const int qd   = lane & 3;
    const int r4   = lane >> 2;
    const int lrow = ((lane >> 3) & 1) * 8 + (lane & 7);
    const int lcol = (lane >> 4) * 8;
    const int bh = blockIdx.y;
    const int b  = bh >> 4;
    const int h  = bh & 15;
    const int q0 = blockIdx.x * 64;

    // static shift: scale * log2(e)
    const float cs = __expf(fminf(lscale[h], 4.6051702f)) * 1.44269504f;

    const size_t rowbase = (size_t)bh * N_ * DH;

    const int row  = tid >> 1;
    const int half = tid & 1;
    const uint32_t sRow = (uint32_t)(row * ALDB + half * 64);

    // ---- Q tile (cp.async, once) ----
    {
        const size_t off = (rowbase + (size_t)(q0 + row) * DH) * 2 + half * 64;
#pragma unroll
        for (int i = 0; i < 4; i++) {
            cp16(sb + AS_QH + sRow + i * 16, (const char*)g_qh + off + i * 16);
            cp16(sb + AS_QL + sRow + i * 16, (const char*)g_ql + off + i * 16);
        }
    }
    auto issue_kv = [&](int j0) {
        const size_t off = (rowbase + (size_t)(j0 + row) * DH) * 2 + half * 64;
#pragma unroll
        for (int i = 0; i < 4; i++) {
            cp16(sb + AS_KH + sRow + i * 16, (const char*)g_kh + off + i * 16);
            cp16(sb + AS_KL + sRow + i * 16, (const char*)g_kl + off + i * 16);
            cp16(sb + AS_VH + sRow + i * 16, (const char*)g_vh + off + i * 16);
            cp16(sb + AS_VL + sRow + i * 16, (const char*)g_vl + off + i * 16);
        }
        CP_COMMIT();
    };
    issue_kv(0);

    float o[8][4];
#pragma unroll
    for (int dn = 0; dn < 8; dn++)
#pragma unroll
        for (int j = 0; j < 4; j++) o[dn][j] = 0.f;
    float lsum0 = 0.f, lsum1 = 0.f;

    for (int j0 = 0; j0 < N_; j0 += 64) {
        CP_WAIT0();
        __syncthreads();

        // ---- S = Q K^T (EC) ----
        float s[8][4];
#pragma unroll
        for (int nt = 0; nt < 8; nt++)
#pragma unroll
            for (int j = 0; j < 4; j++) s[nt][j] = 0.f;

#pragma unroll
        for (int ks = 0; ks < 4; ks++) {
            uint32_t aqh[4], aql[4];
            const uint32_t abase = sb +
                (uint32_t)((wid * 16 + lrow) * ALDB + (ks * 16 + lcol) * 2);
            ldsm_x4(aqh, abase + AS_QH);
            ldsm_x4(aql, abase + AS_QL);
#pragma unroll
            for (int p = 0; p < 4; p++) {
                const uint32_t bbase = sb +
                    (uint32_t)((p * 16 + lrow) * ALDB + (ks * 16 + lcol) * 2);
                uint32_t kh[4], kl[4];
                ldsm_x4(kh, bbase + AS_KH);
                ldsm_x4(kl, bbase + AS_KL);
                mma_bf16(s[2 * p],     aqh, kh[0], kh[2]);
                mma_bf16(s[2 * p + 1], aqh, kh[1], kh[3]);
                mma_bf16(s[2 * p],     aqh, kl[0], kl[2]);
                mma_bf16(s[2 * p + 1], aqh, kl[1], kl[3]);
                mma_bf16(s[2 * p],     aql, kh[0], kh[2]);
                mma_bf16(s[2 * p + 1], aql, kh[1], kh[3]);
            }
        }

        // ---- static-shift softmax numerators ----
#pragma unroll
        for (int nt = 0; nt < 8; nt++) {
            s[nt][0] = exp2f(s[nt][0] - cs);
            s[nt][1] = exp2f(s[nt][1] - cs);
            s[nt][2] = exp2f(s[nt][2] - cs);
            s[nt][3] = exp2f(s[nt][3] - cs);
            lsum0 += s[nt][0] + s[nt][1];
            lsum1 += s[nt][2] + s[nt][3];
        }

        // ---- O += P V (EC, V B-frags via ldmatrix.trans) ----
#pragma unroll
        for (int kt = 0; kt < 4; kt++) {
            const int u = 2 * kt, v2 = 2 * kt + 1;
            uint32_t pah[4], pal[4];
            pah[0] = pack_bf16(s[u][0],  s[u][1]);
            pah[1] = pack_bf16(s[u][2],  s[u][3]);
            pah[2] = pack_bf16(s[v2][0], s[v2][1]);
            pah[3] = pack_bf16(s[v2][2], s[v2][3]);
            pal[0] = pack_bf16(s[u][0]  - bf16_round(s[u][0]),  s[u][1]  - bf16_round(s[u][1]));
            pal[1] = pack_bf16(s[u][2]  - bf16_round(s[u][2]),  s[u][3]  - bf16_round(s[u][3]));
            pal[2] = pack_bf16(s[v2][0] - bf16_round(s[v2][0]), s[v2][1] - bf16_round(s[v2][1]));
            pal[3] = pack_bf16(s[v2][2] - bf16_round(s[v2][2]), s[v2][3] - bf16_round(s[v2][3]));
#pragma unroll
            for (int p = 0; p < 4; p++) {
                const uint32_t vbase = sb +
                    (uint32_t)((kt * 16 + lrow) * ALDB + (p * 16 + lcol) * 2);
                uint32_t vh[4], vl[4];
                ldsm_x4_t(vh, vbase + AS_VH);
                ldsm_x4_t(vl, vbase + AS_VL);
                mma_bf16(o[2 * p],     pah, vh[0], vh[1]);
                mma_bf16(o[2 * p + 1], pah, vh[2], vh[3]);
                mma_bf16(o[2 * p],     pah, vl[0], vl[1]);
                mma_bf16(o[2 * p + 1], pah, vl[2], vl[3]);
                mma_bf16(o[2 * p],     pal, vh[0], vh[1]);
                mma_bf16(o[2 * p + 1], pal, vh[2], vh[3]);
            }
        }
        __syncthreads();
        if (j0 + 64 < N_) issue_kv(j0 + 64);
    }

    // ---- final row-sum reduction across the quad, then normalize ----
    lsum0 += __shfl_xor_sync(0xffffffffu, lsum0, 1);
    lsum0 += __shfl_xor_sync(0xffffffffu, lsum0, 2);
    lsum1 += __shfl_xor_sync(0xffffffffu, lsum1, 1);
    lsum1 += __shfl_xor_sync(0xffffffffu, lsum1, 2);
    const float inv0 = 1.f / lsum0;
    const float inv1 = 1.f / lsum1;
#pragma unroll
    for (int dn = 0; dn < 8; dn++) {
        const int d = dn * 8 + qd * 2;
#pragma unroll
        for (int rr = 0; rr < 2; rr++) {
            const int n = q0 + wid * 16 + r4 + rr * 8;
            const float inv = rr ? inv1 : inv0;
            const float f0 = o[dn][rr * 2 + 0] * inv;
            const float f1 = o[dn][rr * 2 + 1] * inv;
            const size_t idx = (size_t)(b * N_ + n) * DM + h * 64 + d;
            *(uint32_t*)(g_aoh + idx) = pack_bf16(f0, f1);
            *(uint32_t*)(g_aol + idx) = pack_bf16(f0 - bf16_round(f0), f1 - bf16_round(f1));
        }
    }
}

// ---------------------------------------------------------------------------
extern "C" void kernel_launch(void* const* d_in, const int* in_sizes, int n_in,
                              void* d_out, int out_size)
{
    const float* x      = (const float*)d_in[0];
    const float* w_qkv  = (const float*)d_in[1];
    const float* b_qkv  = (const float*)d_in[2];
    const float* w_out  = (const float*)d_in[3];
    const float* lscale = (const float*)d_in[4];
    float* out = (float*)d_out;

    bf16 *xh, *xl, *wqh, *wql, *woh, *wol, *aoh, *aol;
    cudaGetSymbolAddress((void**)&xh,  g_x_hi);
    cudaGetSymbolAddress((void**)&xl,  g_x_lo);
    cudaGetSymbolAddress((void**)&wqh, g_wq_hi);
    cudaGetSymbolAddress((void**)&wql, g_wq_lo);
    cudaGetSymbolAddress((void**)&woh, g_wo_hi);
    cudaGetSymbolAddress((void**)&wol, g_wo_lo);
    cudaGetSymbolAddress((void**)&aoh, g_aoh);
    cudaGetSymbolAddress((void**)&aol, g_aol);

    cudaFuncSetAttribute(gemm_mma_kernel, cudaFuncAttributeMaxDynamicSharedMemorySize, GS_TOTAL);
    cudaFuncSetAttribute(attn_mma_kernel, cudaFuncAttributeMaxDynamicSharedMemorySize, AS_TOTAL);

    // 0. decompose inputs
    decomp_kernel<<<(M_TOT * DM) / 1024, 256>>>(x,     xh,  xl);
    decomp_kernel<<<(QKV_N * DM) / 1024, 256>>>(w_qkv, wqh, wql);
    decomp_kernel<<<(DM * DM)    / 1024, 256>>>(w_out, woh, wol);

    // 1. QKV projection: q,k -> float; v -> bf16 hi/lo
    dim3 g1(QKV_N / 128, M_TOT / 128);     // (24, 64)
    gemm_mma_kernel<<<g1, 256, GS_TOTAL>>>(xh, xl, wqh, wql, b_qkv, nullptr, 0);

    // 2. normalize q (scale*log2e folded) and k, emit hi/lo
    l2norm_kernel<<<NROWS / 8, 256>>>(lscale, 0);
    l2norm_kernel<<<NROWS / 8, 256>>>(lscale, 1);

    // 3. flash attention -> ao hi/lo
    dim3 g3(N_ / 64, B_ * H_);             // (32, 64)
    attn_mma_kernel<<<g3, 128, AS_TOTAL>>>(lscale);

    // 4. output projection -> d_out
    dim3 g4(DM / 128, M_TOT / 128);        // (8, 64)
    gemm_mma_kernel<<<g4, 256, GS_TOTAL>>>(aoh, aol, woh, wol, nullptr, out, 1);
}

// round 9
// speedup vs baseline: 1.7637x; 1.1646x over previous
#include <cuda_runtime.h>
#include <cuda_bf16.h>
#include <math.h>
#include <stdint.h>

#define B_    4
#define N_    2048
#define H_    16
#define DH    64
#define DM    1024
#define M_TOT (B_ * N_)        // 8192
#define QKV_N (3 * DM)         // 3072
#define NROWS (B_ * H_ * N_)   // 131072

typedef __nv_bfloat16 bf16;

// ---------------------------------------------------------------------------
// Scratch (static device globals — allocation-free per harness rules)
// ---------------------------------------------------------------------------
__device__ float g_q [(size_t)NROWS * DH];
__device__ float g_k [(size_t)NROWS * DH];

__device__ bf16 g_qh[(size_t)NROWS * DH];   // normalized q * scale * log2(e), hi/lo
__device__ bf16 g_ql[(size_t)NROWS * DH];
__device__ bf16 g_kh[(size_t)NROWS * DH];
__device__ bf16 g_kl[(size_t)NROWS * DH];
__device__ bf16 g_vh[(size_t)NROWS * DH];
__device__ bf16 g_vl[(size_t)NROWS * DH];

__device__ bf16 g_x_hi [(size_t)M_TOT * DM];
__device__ bf16 g_x_lo [(size_t)M_TOT * DM];
__device__ bf16 g_wq_hi[(size_t)QKV_N * DM];
__device__ bf16 g_wq_lo[(size_t)QKV_N * DM];
__device__ bf16 g_wo_hi[(size_t)DM * DM];
__device__ bf16 g_wo_lo[(size_t)DM * DM];
__device__ bf16 g_aoh[(size_t)M_TOT * DM];
__device__ bf16 g_aol[(size_t)M_TOT * DM];

// ---------------------------------------------------------------------------
// Helpers
// ---------------------------------------------------------------------------
__device__ __forceinline__ void mma_bf16(float* c, const uint32_t* a,
                                         uint32_t b0, uint32_t b1) {
    asm volatile(
        "mma.sync.aligned.m16n8k16.row.col.f32.bf16.bf16.f32 "
        "{%0,%1,%2,%3}, {%4,%5,%6,%7}, {%8,%9}, {%0,%1,%2,%3};\n"
        : "+f"(c[0]), "+f"(c[1]), "+f"(c[2]), "+f"(c[3])
        : "r"(a[0]), "r"(a[1]), "r"(a[2]), "r"(a[3]), "r"(b0), "r"(b1));
}
__device__ __forceinline__ uint32_t pack_bf16(float x, float y) {
    __nv_bfloat162 t = __floats2bfloat162_rn(x, y);
    return *(uint32_t*)&t;
}
__device__ __forceinline__ float bf16_round(float x) {
    return __bfloat162float(__float2bfloat16_rn(x));
}
__device__ __forceinline__ uint32_t smem_u32(const void* p) {
    uint32_t a;
    asm("{ .reg .u64 t; cvta.to.shared.u64 t, %1; cvt.u32.u64 %0, t; }" : "=r"(a) : "l"(p));
    return a;
}
__device__ __forceinline__ void cp16(uint32_t dst, const void* src) {
    asm volatile("cp.async.cg.shared.global [%0], [%1], 16;" :: "r"(dst), "l"(src));
}
#define CP_COMMIT() asm volatile("cp.async.commit_group;" ::: "memory")
#define CP_WAIT0()  asm volatile("cp.async.wait_group 0;" ::: "memory")
#define CP_WAIT2()  asm volatile("cp.async.wait_group 2;" ::: "memory")

__device__ __forceinline__ void ldsm_x4(uint32_t* r, uint32_t addr) {
    asm volatile("ldmatrix.sync.aligned.m8n8.x4.shared.b16 {%0,%1,%2,%3}, [%4];"
                 : "=r"(r[0]), "=r"(r[1]), "=r"(r[2]), "=r"(r[3]) : "r"(addr));
}
__device__ __forceinline__ void ldsm_x4_t(uint32_t* r, uint32_t addr) {
    asm volatile("ldmatrix.sync.aligned.m8n8.x4.trans.shared.b16 {%0,%1,%2,%3}, [%4];"
                 : "=r"(r[0]), "=r"(r[1]), "=r"(r[2]), "=r"(r[3]) : "r"(addr));
}

// ---------------------------------------------------------------------------
// f32 -> (bf16 hi, bf16 lo).  4 elems / thread.
// ---------------------------------------------------------------------------
__global__ __launch_bounds__(256) void decomp_kernel(
    const float* __restrict__ src, bf16* __restrict__ hi, bf16* __restrict__ lo)
{
    size_t i = ((size_t)blockIdx.x * 256 + threadIdx.x) * 4;
    float4 v = *(const float4*)(src + i);
    float h0 = bf16_round(v.x), h1 = bf16_round(v.y);
    float h2 = bf16_round(v.z), h3 = bf16_round(v.w);
    *(uint32_t*)(hi + i)     = pack_bf16(v.x, v.y);
    *(uint32_t*)(hi + i + 2) = pack_bf16(v.z, v.w);
    *(uint32_t*)(lo + i)     = pack_bf16(v.x - h0, v.y - h1);
    *(uint32_t*)(lo + i + 2) = pack_bf16(v.z - h2, v.w - h3);
}

// ---------------------------------------------------------------------------
// EC bf16 GEMM, 4-stage cp.async pipeline, K-chunk 16, ldmatrix frags.
// Block 128x128, 256 thr (8 warps 4x2), 2 CTAs/SM.  One barrier per chunk.
// Row stride 48 B (16-B aligned; 12-word stride covers all 32 banks per
// 8 rows -> ldmatrix conflict-free).
// ---------------------------------------------------------------------------
#define GLDB  48
#define G4_ARR   (128 * GLDB)               // 6144 B
#define G4_AH 0
#define G4_AL (1 * G4_ARR)
#define G4_BH (2 * G4_ARR)
#define G4_BL (3 * G4_ARR)
#define G4_STAGE (4 * G4_ARR)               // 24576 B
#define GS_TOTAL (4 * G4_STAGE)             // 98304 B

__global__ __launch_bounds__(256, 2) void gemm_mma_kernel(
    const bf16* __restrict__ Ahi, const bf16* __restrict__ Alo,
    const bf16* __restrict__ Bhi, const bf16* __restrict__ Blo,
    const float* __restrict__ bias, float* __restrict__ Cout, int mode)
{
    extern __shared__ char smem[];
    const uint32_t sb = smem_u32(smem);
    const int tid  = threadIdx.x;
    const int wid  = tid >> 5;
    const int lane = tid & 31;
    const int wm   = wid & 3;
    const int wn   = wid >> 2;
    const int qd   = lane & 3;
    const int r4   = lane >> 2;
    const int m0 = blockIdx.y * 128;
    const int n0 = blockIdx.x * 128;

    const int lrow = ((lane >> 3) & 1) * 8 + (lane & 7);
    const int lcol = (lane >> 4) * 8;       // halfwords (0 or 8)

    float c[2][8][4];
#pragma unroll
    for (int mt = 0; mt < 2; mt++)
#pragma unroll
        for (int nt = 0; nt < 8; nt++)
#pragma unroll
            for (int j = 0; j < 4; j++) c[mt][nt][j] = 0.f;

    const int row  = tid >> 1;              // 0..127
    const int half = tid & 1;               // 16-B half of the 32-B row
    const size_t gA0 = (size_t)(m0 + row) * DM * 2 + half * 16;
    const size_t gB0 = (size_t)(n0 + row) * DM * 2 + half * 16;
    const uint32_t sRow = (uint32_t)(row * GLDB + half * 16);

    auto issue = [&](int ch) {
        const size_t ko = (size_t)ch * 32;          // 16 bf16 = 32 B
        const uint32_t s = sb + (ch & 3) * G4_STAGE + sRow;
        cp16(s + G4_AH, (const char*)Ahi + gA0 + ko);
        cp16(s + G4_AL, (const char*)Alo + gA0 + ko);
        cp16(s + G4_BH, (const char*)Bhi + gB0 + ko);
        cp16(s + G4_BL, (const char*)Blo + gB0 + ko);
        CP_COMMIT();
    };

    issue(0); issue(1); issue(2);

    for (int ch = 0; ch < 64; ch++) {
        CP_WAIT2();                     // group ch complete (ch+1, ch+2 in flight)
        __syncthreads();

        const uint32_t sbuf = sb + (ch & 3) * G4_STAGE;
        uint32_t ah[2][4], al[2][4];
#pragma unroll
        for (int mt = 0; mt < 2; mt++) {
            const uint32_t abase = sbuf +
                (uint32_t)((wm * 32 + mt * 16 + lrow) * GLDB + lcol * 2);
            ldsm_x4(ah[mt], abase + G4_AH);
            ldsm_x4(al[mt], abase + G4_AL);
        }
#pragma unroll
        for (int p = 0; p < 4; p++) {
            const uint32_t bbase = sbuf +
                (uint32_t)((wn * 64 + p * 16 + lrow) * GLDB + lcol * 2);
            uint32_t bh[4], bl[4];
            ldsm_x4(bh, bbase + G4_BH);
            ldsm_x4(bl, bbase + G4_BL);
#pragma unroll
            for (int mt = 0; mt < 2; mt++) {
                mma_bf16(c[mt][2 * p],     ah[mt], bh[0], bh[2]);
                mma_bf16(c[mt][2 * p + 1], ah[mt], bh[1], bh[3]);
            }
#pragma unroll
            for (int mt = 0; mt < 2; mt++) {
                mma_bf16(c[mt][2 * p],     ah[mt], bl[0], bl[2]);
                mma_bf16(c[mt][2 * p + 1], ah[mt], bl[1], bl[3]);
            }
#pragma unroll
            for (int mt = 0; mt < 2; mt++) {
                mma_bf16(c[mt][2 * p],     al[mt], bh[0], bh[2]);
                mma_bf16(c[mt][2 * p + 1], al[mt], bh[1], bh[3]);
            }
        }
        if (ch + 3 < 64) issue(ch + 3);   // writes slot (ch-1)&3; readers done
    }

    // ---- epilogue ----
#pragma unroll
    for (int nt = 0; nt < 8; nt++) {
        const int nb = n0 + wn * 64 + nt * 8 + qd * 2;
        if (mode == 0) {
            const int which = nb >> 10;
            const int rem   = nb & 1023;
            const int hh    = rem >> 6;
            const int d     = rem & 63;
            const float b0 = bias[nb], b1 = bias[nb + 1];
#pragma unroll
            for (int mt = 0; mt < 2; mt++) {
#pragma unroll
                for (int rr = 0; rr < 2; rr++) {
                    const int m = m0 + wm * 32 + mt * 16 + r4 + rr * 8;
                    const int bidx = m >> 11, ntok = m & 2047;
                    const size_t sidx = ((size_t)(bidx * H_ + hh) * N_ + ntok) * DH + d;
                    float f0 = c[mt][nt][rr * 2 + 0] + b0;
                    float f1 = c[mt][nt][rr * 2 + 1] + b1;
                    if (which == 0)      *(float2*)(g_q + sidx) = make_float2(f0, f1);
                    else if (which == 1) *(float2*)(g_k + sidx) = make_float2(f0, f1);
                    else {
                        *(uint32_t*)(g_vh + sidx) = pack_bf16(f0, f1);
                        *(uint32_t*)(g_vl + sidx) = pack_bf16(f0 - bf16_round(f0),
                                                              f1 - bf16_round(f1));
                    }
                }
            }
        } else {
#pragma unroll
            for (int mt = 0; mt < 2; mt++) {
#pragma unroll
                for (int rr = 0; rr < 2; rr++) {
                    const int m = m0 + wm * 32 + mt * 16 + r4 + rr * 8;
                    *(float2*)(Cout + (size_t)m * DM + nb) =
                        make_float2(c[mt][nt][rr * 2 + 0], c[mt][nt][rr * 2 + 1]);
                }
            }
        }
    }
}

// ---------------------------------------------------------------------------
// L2 normalize + bf16 hi/lo emit. blockIdx.y 0: q (scale*log2e folded), 1: k.
// ---------------------------------------------------------------------------
__global__ __launch_bounds__(256) void l2norm_kernel(const float* __restrict__ lscale)
{
    const int which = blockIdx.y;
    const int warp = (blockIdx.x * blockDim.x + threadIdx.x) >> 5;
    const int lane = threadIdx.x & 31;
    if (warp >= NROWS) return;
    const float* row = (which ? g_k : g_q) + (size_t)warp * DH;
    float2 v = *(const float2*)(row + 2 * lane);
    float ss = v.x * v.x + v.y * v.y;
#pragma unroll
    for (int off = 16; off >= 1; off >>= 1)
        ss += __shfl_xor_sync(0xffffffffu, ss, off);
    float sc = 1.f;
    if (which == 0) {
        const int h = (warp >> 11) & (H_ - 1);
        sc = __expf(fminf(lscale[h], 4.6051702f)) * 1.44269504f;   // scale * log2(e)
    }
    const float inv = sc / fmaxf(sqrtf(ss), 1e-12f);
    const float f0 = v.x * inv, f1 = v.y * inv;
    bf16* hi = which ? g_kh : g_qh;
    bf16* lo = which ? g_kl : g_ql;
    const size_t idx = (size_t)warp * DH + 2 * lane;
    *(uint32_t*)(hi + idx) = pack_bf16(f0, f1);
    *(uint32_t*)(lo + idx) = pack_bf16(f0 - bf16_round(f0), f1 - bf16_round(f1));
}

// ---------------------------------------------------------------------------
// Flash attention, EC bf16 mma.sync + ldmatrix, static-max softmax.
// CTA = 256 thr (8 warps), Q block 128, K tile 64, KV DOUBLE-buffered.
// smem: Q 2x18432 + KV 2 stages x 4 x 9216 = 110592 B -> 2 CTAs/SM.
// ---------------------------------------------------------------------------
#define ALDB 144
#define AS_QH 0
#define AS_QL (AS_QH + 128 * ALDB)
#define AS_KV (AS_QL + 128 * ALDB)            // 36864
#define KV_ARR   (64 * ALDB)                  // 9216
#define KV_STAGE (4 * KV_ARR)                 // 36864
#define KV_KH 0
#define KV_KL (1 * KV_ARR)
#define KV_VH (2 * KV_ARR)
#define KV_VL (3 * KV_ARR)
#define AS_TOTAL (AS_KV + 2 * KV_STAGE)       // 110592 B

__global__ __launch_bounds__(256, 2) void attn_mma_kernel(const float* __restrict__ lscale)
{
    extern __shared__ char smem[];
    const uint32_t sb = smem_u32(smem);
    const int tid  = threadIdx.x;
    const int wid  = tid >> 5;                 // 0..7 -> q rows wid*16
    const int lane = tid & 31;
    const int qd   = lane & 3;
    const int r4   = lane >> 2;
    const int lrow = ((lane >> 3) & 1) * 8 + (lane & 7);
    const int lcol = (lane >> 4) * 8;
    const int bh = blockIdx.y;
    const int b  = bh >> 4;
    const int h  = bh & 15;
    const int q0 = blockIdx.x * 128;

    const float cs = __expf(fminf(lscale[h], 4.6051702f)) * 1.44269504f;

    const size_t rowbase = (size_t)bh * N_ * DH;

    // ---- Q tile (cp.async, once): 128 rows, 2 threads/row ----
    {
        const int r = tid >> 1, hf = tid & 1;
        const size_t off = (rowbase + (size_t)(q0 + r) * DH) * 2 + hf * 64;
        const uint32_t sq = sb + (uint32_t)(r * ALDB + hf * 64);
#pragma unroll
        for (int i = 0; i < 4; i++) {
            cp16(sq + AS_QH + i * 16, (const char*)g_qh + off + i * 16);
            cp16(sq + AS_QL + i * 16, (const char*)g_ql + off + i * 16);
        }
    }
    // ---- KV tile issue: 64 rows, 4 threads/row (32 B each) ----
    const int kr = tid >> 2;
    const int kq = (tid & 3) * 32;
    auto issue_kv = [&](int j0, int buf) {
        const size_t off = (rowbase + (size_t)(j0 + kr) * DH) * 2 + kq;
        const uint32_t s = sb + AS_KV + buf * KV_STAGE + (uint32_t)(kr * ALDB + kq);
#pragma unroll
        for (int i = 0; i < 2; i++) {
            cp16(s + KV_KH + i * 16, (const char*)g_kh + off + i * 16);
            cp16(s + KV_KL + i * 16, (const char*)g_kl + off + i * 16);
            cp16(s + KV_VH + i * 16, (const char*)g_vh + off + i * 16);
            cp16(s + KV_VL + i * 16, (const char*)g_vl + off + i * 16);
        }
        CP_COMMIT();
    };
    issue_kv(0, 0);

    float o[8][4];
#pragma unroll
    for (int dn = 0; dn < 8; dn++)
#pragma unroll
        for (int j = 0; j < 4; j++) o[dn][j] = 0.f;
    float lsum0 = 0.f, lsum1 = 0.f;

    for (int t = 0; t < N_ / 64; t++) {
        CP_WAIT0();
        __syncthreads();
        const uint32_t kvb = sb + AS_KV + (t & 1) * KV_STAGE;

        // ---- S = Q K^T (EC) ----
        float s[8][4];
#pragma unroll
        for (int nt = 0; nt < 8; nt++)
#pragma unroll
            for (int j = 0; j < 4; j++) s[nt][j] = 0.f;

#pragma unroll
        for (int ks = 0; ks < 4; ks++) {
            uint32_t aqh[4], aql[4];
            const uint32_t abase = sb +
                (uint32_t)((wid * 16 + lrow) * ALDB + (ks * 16 + lcol) * 2);
            ldsm_x4(aqh, abase + AS_QH);
            ldsm_x4(aql, abase + AS_QL);
#pragma unroll
            for (int p = 0; p < 4; p++) {
                const uint32_t bbase = kvb +
                    (uint32_t)((p * 16 + lrow) * ALDB + (ks * 16 + lcol) * 2);
                uint32_t kh[4], kl[4];
                ldsm_x4(kh, bbase + KV_KH);
                ldsm_x4(kl, bbase + KV_KL);
                mma_bf16(s[2 * p],     aqh, kh[0], kh[2]);
                mma_bf16(s[2 * p + 1], aqh, kh[1], kh[3]);
                mma_bf16(s[2 * p],     aqh, kl[0], kl[2]);
                mma_bf16(s[2 * p + 1], aqh, kl[1], kl[3]);
                mma_bf16(s[2 * p],     aql, kh[0], kh[2]);
                mma_bf16(s[2 * p + 1], aql, kh[1], kh[3]);
            }
        }

        // ---- static-shift softmax numerators ----
#pragma unroll
        for (int nt = 0; nt < 8; nt++) {
            s[nt][0] = exp2f(s[nt][0] - cs);
            s[nt][1] = exp2f(s[nt][1] - cs);
            s[nt][2] = exp2f(s[nt][2] - cs);
            s[nt][3] = exp2f(s[nt][3] - cs);
            lsum0 += s[nt][0] + s[nt][1];
            lsum1 += s[nt][2] + s[nt][3];
        }

        // ---- O += P V (EC, V B-frags via ldmatrix.trans) ----
#pragma unroll
        for (int kt = 0; kt < 4; kt++) {
            const int u = 2 * kt, v2 = 2 * kt + 1;
            uint32_t pah[4], pal[4];
            pah[0] = pack_bf16(s[u][0],  s[u][1]);
            pah[1] = pack_bf16(s[u][2],  s[u][3]);
            pah[2] = pack_bf16(s[v2][0], s[v2][1]);
            pah[3] = pack_bf16(s[v2][2], s[v2][3]);
            pal[0] = pack_bf16(s[u][0]  - bf16_round(s[u][0]),  s[u][1]  - bf16_round(s[u][1]));
            pal[1] = pack_bf16(s[u][2]  - bf16_round(s[u][2]),  s[u][3]  - bf16_round(s[u][3]));
            pal[2] = pack_bf16(s[v2][0] - bf16_round(s[v2][0]), s[v2][1] - bf16_round(s[v2][1]));
            pal[3] = pack_bf16(s[v2][2] - bf16_round(s[v2][2]), s[v2][3] - bf16_round(s[v2][3]));
#pragma unroll
            for (int p = 0; p < 4; p++) {
                const uint32_t vbase = kvb +
                    (uint32_t)((kt * 16 + lrow) * ALDB + (p * 16 + lcol) * 2);
                uint32_t vh[4], vl[4];
                ldsm_x4_t(vh, vbase + KV_VH);
                ldsm_x4_t(vl, vbase + KV_VL);
                mma_bf16(o[2 * p],     pah, vh[0], vh[1]);
                mma_bf16(o[2 * p + 1], pah, vh[2], vh[3]);
                mma_bf16(o[2 * p],     pah, vl[0], vl[1]);
                mma_bf16(o[2 * p + 1], pah, vl[2], vl[3]);
                mma_bf16(o[2 * p],     pal, vh[0], vh[1]);
                mma_bf16(o[2 * p + 1], pal, vh[2], vh[3]);
            }
        }
        if (t + 1 < N_ / 64) issue_kv((t + 1) * 64, (t + 1) & 1);
    }

    // ---- final row-sum reduction across the quad, then normalize ----
    lsum0 += __shfl_xor_sync(0xffffffffu, lsum0, 1);
    lsum0 += __shfl_xor_sync(0xffffffffu, lsum0, 2);
    lsum1 += __shfl_xor_sync(0xffffffffu, lsum1, 1);
    lsum1 += __shfl_xor_sync(0xffffffffu, lsum1, 2);
    const float inv0 = 1.f / lsum0;
    const float inv1 = 1.f / lsum1;
#pragma unroll
    for (int dn = 0; dn < 8; dn++) {
        const int d = dn * 8 + qd * 2;
#pragma unroll
        for (int rr = 0; rr < 2; rr++) {
            const int n = q0 + wid * 16 + r4 + rr * 8;
            const float inv = rr ? inv1 : inv0;
            const float f0 = o[dn][rr * 2 + 0] * inv;
            const float f1 = o[dn][rr * 2 + 1] * inv;
            const size_t idx = (size_t)(b * N_ + n) * DM + h * 64 + d;
            *(uint32_t*)(g_aoh + idx) = pack_bf16(f0, f1);
            *(uint32_t*)(g_aol + idx) = pack_bf16(f0 - bf16_round(f0), f1 - bf16_round(f1));
        }
    }
}

// ---------------------------------------------------------------------------
extern "C" void kernel_launch(void* const* d_in, const int* in_sizes, int n_in,
                              void* d_out, int out_size)
{
    const float* x      = (const float*)d_in[0];
    const float* w_qkv  = (const float*)d_in[1];
    const float* b_qkv  = (const float*)d_in[2];
    const float* w_out  = (const float*)d_in[3];
    const float* lscale = (const float*)d_in[4];
    float* out = (float*)d_out;

    bf16 *xh, *xl, *wqh, *wql, *woh, *wol, *aoh, *aol;
    cudaGetSymbolAddress((void**)&xh,  g_x_hi);
    cudaGetSymbolAddress((void**)&xl,  g_x_lo);
    cudaGetSymbolAddress((void**)&wqh, g_wq_hi);
    cudaGetSymbolAddress((void**)&wql, g_wq_lo);
    cudaGetSymbolAddress((void**)&woh, g_wo_hi);
    cudaGetSymbolAddress((void**)&wol, g_wo_lo);
    cudaGetSymbolAddress((void**)&aoh, g_aoh);
    cudaGetSymbolAddress((void**)&aol, g_aol);

    cudaFuncSetAttribute(gemm_mma_kernel, cudaFuncAttributeMaxDynamicSharedMemorySize, GS_TOTAL);
    cudaFuncSetAttribute(attn_mma_kernel, cudaFuncAttributeMaxDynamicSharedMemorySize, AS_TOTAL);

    // 0. decompose inputs
    decomp_kernel<<<(M_TOT * DM) / 1024, 256>>>(x,     xh,  xl);
    decomp_kernel<<<(QKV_N * DM) / 1024, 256>>>(w_qkv, wqh, wql);
    decomp_kernel<<<(DM * DM)    / 1024, 256>>>(w_out, woh, wol);

    // 1. QKV projection: q,k -> float; v -> bf16 hi/lo
    dim3 g1(QKV_N / 128, M_TOT / 128);     // (24, 64)
    gemm_mma_kernel<<<g1, 256, GS_TOTAL>>>(xh, xl, wqh, wql, b_qkv, nullptr, 0);

    // 2. normalize q (scale*log2e folded) and k, emit hi/lo (one launch)
    dim3 g2(NROWS / 8, 2);
    l2norm_kernel<<<g2, 256>>>(lscale);

    // 3. flash attention -> ao hi/lo
    dim3 g3(N_ / 128, B_ * H_);            // (16, 64)
    attn_mma_kernel<<<g3, 256, AS_TOTAL>>>(lscale);

    // 4. output projection -> d_out
    dim3 g4(DM / 128, M_TOT / 128);        // (8, 64)
    gemm_mma_kernel<<<g4, 256, GS_TOTAL>>>(aoh, aol, woh, wol, nullptr, out, 1);
}